// round 4
// baseline (speedup 1.0000x reference)
#include <cuda_runtime.h>
#include <math.h>

#define TOTP 500000
#define BATCH 64
#define KTOT 398
#define CLIP0 1.0f
#define CLIP1 1.0f

// ---------------- scratch (device globals; no allocations) ----------------
__device__ float g_E[BATCH * KTOT];           // embeddings [64][398]
__device__ float g_rsq[BATCH];                // per-row residual sum of squares
__device__ __align__(16) float g_resid[(size_t)BATCH * TOTP]; // residual scratch, 128 MB

// ---------------- f32x2 helpers ----------------
__device__ __forceinline__ unsigned long long ffma2(unsigned long long a,
                                                    unsigned long long b,
                                                    unsigned long long c) {
    unsigned long long d;
    asm("fma.rn.f32x2 %0, %1, %2, %3;" : "=l"(d) : "l"(a), "l"(b), "l"(c));
    return d;
}
__device__ __forceinline__ unsigned long long pack2(float x, float y) {
    unsigned long long d;
    asm("mov.b64 %0, {%1, %2};" : "=l"(d) : "f"(x), "f"(y));
    return d;
}
__device__ __forceinline__ float2 unpack2(unsigned long long v) {
    float2 r;
    asm("mov.b64 {%0, %1}, %2;" : "=f"(r.x), "=f"(r.y) : "l"(v));
    return r;
}

// ---------------- init ----------------
__global__ void k_init() {
    int t = blockIdx.x * blockDim.x + threadIdx.x;
    if (t < BATCH * KTOT) g_E[t] = 0.0f;
    if (t < BATCH) g_rsq[t] = 0.0f;
}

// ---------------- GEMM1: E[b][c] += sum_p G[b][pbase+p] * Bm[p][c] ----------------
// Block tile: 64 (batch) x (NT2*32) (cols, padded), split-K over P in chunks.
// 256 threads = 16x16; thread tile = 4 rows x NT2 col-pairs (f32x2).
template <int NT2>
__global__ __launch_bounds__(256) void k_gemm1(
    const float* __restrict__ G, const float* __restrict__ Bm,
    int numP, int pbase, int KG, int koff, int chunk)
{
    constexpr int PADK = NT2 * 32;
    __shared__ float Gs[32][65];       // [k][b], padded to kill bank conflicts
    __shared__ float Bs[32][PADK];     // [k][c]

    const int tid = threadIdx.x;
    const int ty = tid >> 4;           // 0..15 -> rows ty*4 .. ty*4+3
    const int tx = tid & 15;           // 0..15 -> col-pairs tx + 16*j

    const int pstart = blockIdx.x * chunk;
    const int pend   = min(pstart + chunk, numP);

    unsigned long long acc[4][NT2];
#pragma unroll
    for (int i = 0; i < 4; i++)
#pragma unroll
        for (int j = 0; j < NT2; j++) acc[i][j] = 0ULL;

    for (int pt = pstart; pt < pend; pt += 32) {
        // stage G tile: Gs[pp][b] = G[b][pbase + pt + pp]
        {
            const int pp = tid & 31;
            const int b0 = tid >> 5;           // 0..7
            const int p  = pt + pp;
            const bool ok = (p < pend);
#pragma unroll
            for (int i = 0; i < 8; i++) {
                const int b = b0 + i * 8;
                Gs[pp][b] = ok ? G[(size_t)b * TOTP + pbase + p] : 0.0f;
            }
        }
        // stage B tile: Bs[r][c] = Bm[(pt+r)][c], zero-padded
        for (int idx = tid; idx < 32 * PADK; idx += 256) {
            const int r = idx / PADK;
            const int c = idx - r * PADK;
            const int prow = pt + r;
            float v = 0.0f;
            if (c < KG && prow < pend) v = Bm[(size_t)prow * KG + c];
            Bs[r][c] = v;
        }
        __syncthreads();

#pragma unroll
        for (int kk = 0; kk < 32; kk++) {
            unsigned long long a2[4], b2[NT2];
#pragma unroll
            for (int i = 0; i < 4; i++) {
                const float a = Gs[kk][ty * 4 + i];
                a2[i] = pack2(a, a);
            }
#pragma unroll
            for (int j = 0; j < NT2; j++)
                b2[j] = *(const unsigned long long*)&Bs[kk][2 * (tx + 16 * j)];
#pragma unroll
            for (int i = 0; i < 4; i++)
#pragma unroll
                for (int j = 0; j < NT2; j++)
                    acc[i][j] = ffma2(a2[i], b2[j], acc[i][j]);
        }
        __syncthreads();
    }

    // epilogue: atomic accumulate into tiny E
#pragma unroll
    for (int i = 0; i < 4; i++) {
        const int b = ty * 4 + i;
#pragma unroll
        for (int j = 0; j < NT2; j++) {
            const float2 v = unpack2(acc[i][j]);
            const int c = 2 * (tx + 16 * j);
            if (c < KG)     atomicAdd(&g_E[b * KTOT + koff + c],     v.x);
            if (c + 1 < KG) atomicAdd(&g_E[b * KTOT + koff + c + 1], v.y);
        }
    }
}

// ---------------- embed clip + average -> out[0..397] ----------------
__global__ void k_embed(float* __restrict__ out) {
    __shared__ float scale[BATCH];
    const int tid = threadIdx.x;
    if (tid < BATCH) {
        float s = 0.0f;
        for (int j = 0; j < KTOT; j++) {
            const float v = g_E[tid * KTOT + j];
            s += v * v;
        }
        const float n = sqrtf(s);
        const float sc = (n > CLIP0) ? (CLIP0 / n) : 1.0f;
        scale[tid] = sc * (1.0f / BATCH);
    }
    __syncthreads();
    for (int j = tid; j < KTOT; j += blockDim.x) {
        float s = 0.0f;
        for (int b = 0; b < BATCH; b++) s += g_E[b * KTOT + j] * scale[b];
        out[j] = s;
    }
}

// ---------------- GEMM2 + residual + stats ----------------
// approx[b][p] = sum_j E[b][j]*Bm[p][j];  residual = G - approx -> scratch
// also: per-row sum(res^2) -> g_rsq (atomic), colsum(G)/64 -> avg_target segment
// Block tile: 64 (batch) x 128 (p). 256 threads = 16x16; thread = 4 rows x 4 p-pairs.
template <int KGP>   // K padded to multiple of 8
__global__ __launch_bounds__(256) void k_gemm2(
    const float* __restrict__ G, const float* __restrict__ Bm,
    float* __restrict__ out_target, int numP, int pbase, int KG, int koff, int ntiles)
{
    __shared__ float Es[BATCH][KGP];
    __shared__ float Bs[8][130];       // [j][p], transposed stage for p-pair packing
    __shared__ float colsum[128];

    const int tid = threadIdx.x;
    const int ty = tid >> 4;
    const int tx = tid & 15;

    // load E slice for this group (zero-pad j >= KG)
    for (int idx = tid; idx < BATCH * KGP; idx += 256) {
        const int b = idx / KGP;
        const int j = idx - b * KGP;
        Es[b][j] = (j < KG) ? g_E[b * KTOT + koff + j] : 0.0f;
    }

    float rs[4] = {0.f, 0.f, 0.f, 0.f};

    for (int tile = blockIdx.x; tile < ntiles; tile += gridDim.x) {
        const int p0 = tile * 128;
        unsigned long long acc[4][4];
#pragma unroll
        for (int i = 0; i < 4; i++)
#pragma unroll
            for (int q = 0; q < 4; q++) acc[i][q] = 0ULL;

        for (int kt = 0; kt < KGP; kt += 8) {
            __syncthreads();   // protects Bs reuse; first one also orders Es load
            // stage Bs[jj][pp] = Bm[(p0+pp)][kt+jj]
            {
                const int jj  = tid & 7;
                const int ppb = tid >> 3;       // 0..31
                const int j   = kt + jj;
#pragma unroll
                for (int r = 0; r < 4; r++) {
                    const int pp = ppb + r * 32;
                    const int p  = p0 + pp;
                    float v = 0.0f;
                    if (p < numP && j < KG) v = Bm[(size_t)p * KG + j];
                    Bs[jj][pp] = v;
                }
            }
            __syncthreads();
#pragma unroll
            for (int jj = 0; jj < 8; jj++) {
                const int j = kt + jj;
                unsigned long long a2[4], b2[4];
#pragma unroll
                for (int i = 0; i < 4; i++) {
                    const float a = Es[ty * 4 + i][j];
                    a2[i] = pack2(a, a);
                }
#pragma unroll
                for (int q = 0; q < 4; q++)
                    b2[q] = *(const unsigned long long*)&Bs[jj][2 * (tx + 16 * q)];
#pragma unroll
                for (int i = 0; i < 4; i++)
#pragma unroll
                    for (int q = 0; q < 4; q++)
                        acc[i][q] = ffma2(a2[i], b2[q], acc[i][q]);
            }
        }

        // epilogue: residual, rsq, colsum
        if (tid < 128) colsum[tid] = 0.0f;
        __syncthreads();
#pragma unroll
        for (int q = 0; q < 4; q++) {
            const int pp = 2 * (tx + 16 * q);
            const int p  = p0 + pp;
            float2 cs = make_float2(0.f, 0.f);
#pragma unroll
            for (int i = 0; i < 4; i++) {
                const int b = ty * 4 + i;
                float2 gv = make_float2(0.f, 0.f);
                if (p < numP)
                    gv = *(const float2*)&G[(size_t)b * TOTP + pbase + p];
                const float2 a = unpack2(acc[i][q]);
                const float2 r = make_float2(gv.x - a.x, gv.y - a.y);
                if (p < numP)
                    *(float2*)&g_resid[(size_t)b * TOTP + pbase + p] = r;
                rs[i] += r.x * r.x + r.y * r.y;
                cs.x += gv.x; cs.y += gv.y;
            }
            atomicAdd(&colsum[pp],     cs.x);
            atomicAdd(&colsum[pp + 1], cs.y);
        }
        __syncthreads();
        if (tid < 128) {
            const int p = p0 + tid;
            if (p < numP) out_target[p] = colsum[tid] * (1.0f / BATCH);
        }
    }

    // reduce rsq across the 16 tx lanes of each ty group
#pragma unroll
    for (int i = 0; i < 4; i++) {
        float v = rs[i];
#pragma unroll
        for (int off = 8; off > 0; off >>= 1)
            v += __shfl_xor_sync(0xffffffffu, v, off, 16);
        if (tx == 0) atomicAdd(&g_rsq[ty * 4 + i], v);
    }
}

// ---------------- final: clipped residual average -> out[398 .. 398+TOTP) ----------------
// NOTE: out + 398 floats is 8-byte (not 16-byte) aligned -> stores must be float2.
__global__ __launch_bounds__(256) void k_final(float* __restrict__ out_resid) {
    __shared__ float scale[BATCH];
    const int tid = threadIdx.x;
    if (tid < BATCH) {
        const float n = sqrtf(g_rsq[tid]);
        scale[tid] = ((n > CLIP1) ? (CLIP1 / n) : 1.0f) * (1.0f / BATCH);
    }
    __syncthreads();
    const int p4 = blockIdx.x * blockDim.x + tid;   // float4 index
    if (p4 < TOTP / 4) {
        float4 s = make_float4(0.f, 0.f, 0.f, 0.f);
#pragma unroll 4
        for (int b = 0; b < BATCH; b++) {
            const float4 r = *(const float4*)&g_resid[(size_t)b * TOTP + p4 * 4];
            const float sc = scale[b];
            s.x += r.x * sc; s.y += r.y * sc; s.z += r.z * sc; s.w += r.w * sc;
        }
        // two float2 stores: (398 + 4*p4) is even -> 8B aligned; +2 also even.
        *(float2*)&out_resid[p4 * 4]     = make_float2(s.x, s.y);
        *(float2*)&out_resid[p4 * 4 + 2] = make_float2(s.z, s.w);
    }
}

// ---------------- launch ----------------
extern "C" void kernel_launch(void* const* d_in, const int* in_sizes, int n_in,
                              void* d_out, int out_size) {
    (void)in_sizes; (void)n_in; (void)out_size;
    const float* G  = (const float*)d_in[0];
    const float* B0 = (const float*)d_in[1];
    const float* B1 = (const float*)d_in[2];
    const float* B2 = (const float*)d_in[3];
    float* out = (float*)d_out;

    k_init<<<100, 256>>>();

    const int chunk = 512;
    k_gemm1<4><<<(100000 + chunk - 1) / chunk, 256>>>(G, B0, 100000,      0, 104,   0, chunk);
    k_gemm1<5><<<(225000 + chunk - 1) / chunk, 256>>>(G, B1, 225000, 100000, 156, 104, chunk);
    k_gemm1<5><<<(175000 + chunk - 1) / chunk, 256>>>(G, B2, 175000, 325000, 138, 260, chunk);

    k_embed<<<1, 256>>>(out);

    // out layout: [0,398) embed | [398, 398+500000) residual | then target avg
    float* out_tg = out + 398 + TOTP;
    {
        const int nt0 = (100000 + 127) / 128;   // 782
        const int nt1 = (225000 + 127) / 128;   // 1758
        const int nt2 = (175000 + 127) / 128;   // 1368
        k_gemm2<104><<<nt0, 256>>>(G, B0, out_tg +      0, 100000,      0, 104,   0, nt0);
        k_gemm2<160><<<1184, 256>>>(G, B1, out_tg + 100000, 225000, 100000, 156, 104, nt1);
        k_gemm2<144><<<1184, 256>>>(G, B2, out_tg + 325000, 175000, 325000, 138, 260, nt2);
    }

    k_final<<<(TOTP / 4 + 255) / 256, 256>>>(out + 398);
}

// round 6
// speedup vs baseline: 1.7128x; 1.7128x over previous
#include <cuda_runtime.h>
#include <cuda_bf16.h>
#include <cstdint>
#include <math.h>

#define TOTP 500000
#define BATCH 64
#define KTOT 398
#define CLIP0 1.0f
#define CLIP1 1.0f

__device__ float g_E[BATCH * KTOT];
__device__ float g_rsq[BATCH];
__device__ __align__(16) float g_resid[(size_t)BATCH * TOTP];

// ---------------- helpers ----------------
__device__ __forceinline__ uint32_t smem_u32(const void* p) {
    uint32_t a;
    asm("{ .reg .u64 t; cvta.to.shared.u64 t, %1; cvt.u32.u64 %0, t; }" : "=r"(a) : "l"(p));
    return a;
}

// split-bf16: hi = truncated bf16 pair, lo = rn bf16 of remainder pair.
// halfword order: lower half = x (column c), upper half = y (column c+1)
__device__ __forceinline__ void cvt_hilo(float x, float y, uint32_t& hi2, uint32_t& lo2) {
    uint32_t ux = __float_as_uint(x), uy = __float_as_uint(y);
    hi2 = __byte_perm(ux, uy, 0x7632);
    float lx = x - __uint_as_float(ux & 0xFFFF0000u);
    float ly = y - __uint_as_float(uy & 0xFFFF0000u);
    asm("cvt.rn.bf16x2.f32 %0, %1, %2;" : "=r"(lo2) : "f"(ly), "f"(lx));
}

#define LDSM_X4(r, a) \
    asm volatile("ldmatrix.sync.aligned.m8n8.x4.shared.b16 {%0,%1,%2,%3}, [%4];" \
        : "=r"((r)[0]), "=r"((r)[1]), "=r"((r)[2]), "=r"((r)[3]) : "r"(a))
#define LDSM_X4T(r, a) \
    asm volatile("ldmatrix.sync.aligned.m8n8.x4.trans.shared.b16 {%0,%1,%2,%3}, [%4];" \
        : "=r"((r)[0]), "=r"((r)[1]), "=r"((r)[2]), "=r"((r)[3]) : "r"(a))
#define MMA16816(d, a, b0, b1) \
    asm volatile("mma.sync.aligned.m16n8k16.row.col.f32.bf16.bf16.f32 " \
        "{%0,%1,%2,%3}, {%4,%5,%6,%7}, {%8,%9}, {%0,%1,%2,%3};" \
        : "+f"((d)[0]), "+f"((d)[1]), "+f"((d)[2]), "+f"((d)[3]) \
        : "r"((a)[0]), "r"((a)[1]), "r"((a)[2]), "r"((a)[3]), "r"(b0), "r"(b1))

// ---------------- small kernels ----------------
__global__ void k_init() {
    int t = blockIdx.x * blockDim.x + threadIdx.x;
    if (t < BATCH * KTOT) g_E[t] = 0.0f;
    if (t < BATCH) g_rsq[t] = 0.0f;
}

__global__ void k_embed(float* __restrict__ out) {
    __shared__ float scale[BATCH];
    const int tid = threadIdx.x;
    if (tid < BATCH) {
        float s = 0.0f;
        for (int j = 0; j < KTOT; j++) { float v = g_E[tid * KTOT + j]; s += v * v; }
        float n = sqrtf(s);
        scale[tid] = ((n > CLIP0) ? (CLIP0 / n) : 1.0f) * (1.0f / BATCH);
    }
    __syncthreads();
    for (int j = tid; j < KTOT; j += blockDim.x) {
        float s = 0.0f;
        for (int b = 0; b < BATCH; b++) s += g_E[b * KTOT + j] * scale[b];
        out[j] = s;
    }
}

__global__ __launch_bounds__(256) void k_final(float* __restrict__ out_resid) {
    __shared__ float scale[BATCH];
    const int tid = threadIdx.x;
    if (tid < BATCH) {
        float n = sqrtf(g_rsq[tid]);
        scale[tid] = ((n > CLIP1) ? (CLIP1 / n) : 1.0f) * (1.0f / BATCH);
    }
    __syncthreads();
    const int p4 = blockIdx.x * blockDim.x + tid;
    if (p4 < TOTP / 4) {
        float4 s = make_float4(0.f, 0.f, 0.f, 0.f);
#pragma unroll 4
        for (int b = 0; b < BATCH; b++) {
            float4 r = *(const float4*)&g_resid[(size_t)b * TOTP + p4 * 4];
            float sc = scale[b];
            s.x += r.x * sc; s.y += r.y * sc; s.z += r.z * sc; s.w += r.w * sc;
        }
        *(float2*)&out_resid[p4 * 4]     = make_float2(s.x, s.y);
        *(float2*)&out_resid[p4 * 4 + 2] = make_float2(s.z, s.w);
    }
}

// =============== GEMM1 (HMMA): E[b][c] += sum_p G[b][p]*Bm[p][c] ===============
// M=64(batch), N=NPAD, K=p (64 per step, split-K chunks). 8 warps = 4(m16) x 2(n NPAD/2).
template <int KG, int NPAD>
__global__ __launch_bounds__(256, 2) void k_gemm1_mma(
    const float* __restrict__ G, const float* __restrict__ Bm,
    int numP, int pbase, int koff, int chunk)
{
    constexpr int SB = NPAD + 8;                 // b16 stride (conflict-free mod 128B)
    constexpr int NH = NPAD / 2, NT = NH / 8, NG = NT / 2;
    constexpr int OFF_GH = 0, OFF_GL = 9216;
    constexpr int OFF_BH = 18432, OFF_BL = OFF_BH + 64 * SB * 2;

    extern __shared__ __align__(16) char smem[];
    const uint32_t sb32 = smem_u32(smem);
    const int tid = threadIdx.x, wid = tid >> 5, lane = tid & 31;
    const int wr = wid >> 1, wc = wid & 1;

    float acc[NT][4];
#pragma unroll
    for (int t = 0; t < NT; t++)
#pragma unroll
        for (int i = 0; i < 4; i++) acc[t][i] = 0.0f;

    const int pstart = blockIdx.x * chunk;
    const int pend = min(pstart + chunk, numP);

    for (int pt = pstart; pt < pend; pt += 64) {
        // stage G: 64 b-rows x 32 p-pairs (row stride 72 b16 = 36 u32)
        for (int idx = tid; idx < 2048; idx += 256) {
            int b = idx >> 5, pp = idx & 31, p = pt + 2 * pp;
            float2 v = make_float2(0.f, 0.f);
            if (p < pend) v = *(const float2*)&G[(size_t)b * TOTP + pbase + p];
            uint32_t h2, l2; cvt_hilo(v.x, v.y, h2, l2);
            ((uint32_t*)(smem + OFF_GH))[b * 36 + pp] = h2;
            ((uint32_t*)(smem + OFF_GL))[b * 36 + pp] = l2;
        }
        // stage B: 64 k-rows x NPAD/2 c-pairs (native [k][c])
        for (int idx = tid; idx < 64 * (NPAD / 2); idx += 256) {
            int k = idx / (NPAD / 2), h = idx % (NPAD / 2), c = 2 * h, p = pt + k;
            float2 v = make_float2(0.f, 0.f);
            if (p < pend && c < KG) v = *(const float2*)&Bm[(size_t)p * KG + c];
            uint32_t h2, l2; cvt_hilo(v.x, v.y, h2, l2);
            ((uint32_t*)(smem + OFF_BH))[k * (SB / 2) + h] = h2;
            ((uint32_t*)(smem + OFF_BL))[k * (SB / 2) + h] = l2;
        }
        __syncthreads();
#pragma unroll
        for (int kk = 0; kk < 4; kk++) {
            uint32_t ah[4], al[4];
            uint32_t ra = (uint32_t)((wr * 16 + (lane & 15)) * 144 + kk * 32 + (lane >> 4) * 16);
            LDSM_X4(ah, sb32 + OFF_GH + ra);
            LDSM_X4(al, sb32 + OFF_GL + ra);
            uint32_t rb = (uint32_t)((kk * 16 + (lane & 15)) * (SB * 2));
#pragma unroll
            for (int g = 0; g < NG; g++) {
                uint32_t cb = (uint32_t)((wc * NH + g * 16 + (lane >> 4) * 8) * 2);
                uint32_t bh[4], bl[4];
                LDSM_X4T(bh, sb32 + OFF_BH + rb + cb);
                LDSM_X4T(bl, sb32 + OFF_BL + rb + cb);
                MMA16816(acc[2 * g],     ah, bh[0], bh[1]);
                MMA16816(acc[2 * g],     al, bh[0], bh[1]);
                MMA16816(acc[2 * g],     ah, bl[0], bl[1]);
                MMA16816(acc[2 * g + 1], ah, bh[2], bh[3]);
                MMA16816(acc[2 * g + 1], al, bh[2], bh[3]);
                MMA16816(acc[2 * g + 1], ah, bl[2], bl[3]);
            }
        }
        __syncthreads();
    }

    // epilogue: atomic accumulate into g_E
    const int m0 = wr * 16 + (lane >> 2);
#pragma unroll
    for (int t = 0; t < NT; t++) {
        int n0 = wc * NH + t * 8 + (lane & 3) * 2;
        if (n0 < KG) {
            atomicAdd(&g_E[m0 * KTOT + koff + n0], acc[t][0]);
            atomicAdd(&g_E[(m0 + 8) * KTOT + koff + n0], acc[t][2]);
        }
        if (n0 + 1 < KG) {
            atomicAdd(&g_E[m0 * KTOT + koff + n0 + 1], acc[t][1]);
            atomicAdd(&g_E[(m0 + 8) * KTOT + koff + n0 + 1], acc[t][3]);
        }
    }
}

// =============== GEMM2 (HMMA): D[p][b] = sum_k Bm[p][k]*E[b][k] ================
// M = p-tile 64, N = 64(batch). A = Bm native [p][k]; B = E native [b][k].
// Fused: residual -> g_resid, colsum(G) -> out_tg, per-b ||r||^2 -> g_rsq.
template <int KG, int KPAD>
__global__ __launch_bounds__(256, 2) void k_gemm2_mma(
    const float* __restrict__ G, const float* __restrict__ Bm,
    float* __restrict__ out_tg, int numP, int pbase, int koff, int ntiles)
{
    constexpr int SB = KPAD + 8;
    constexpr int KK = KPAD / 16;
    constexpr int ES = 64 * SB * 2;
    constexpr int OFF_EH = 0, OFF_EL = ES, OFF_BH = 2 * ES, OFF_BL = 3 * ES;
    constexpr int OFF_CS = 4 * ES, OFF_RS = 4 * ES + 256;

    extern __shared__ __align__(16) char smem[];
    const uint32_t sb32 = smem_u32(smem);
    float* colsum = (float*)(smem + OFF_CS);
    float* rs_s   = (float*)(smem + OFF_RS);
    const int tid = threadIdx.x, wid = tid >> 5, lane = tid & 31;
    const int wr = wid >> 1, wc = wid & 1;

    // stage E (hi/lo) once; zero rs_s
    for (int idx = tid; idx < 64 * (KPAD / 2); idx += 256) {
        int b = idx / (KPAD / 2), h = idx % (KPAD / 2), k = 2 * h;
        float2 v = make_float2(0.f, 0.f);
        if (k < KG) v = *(const float2*)&g_E[b * KTOT + koff + k];
        uint32_t h2, l2; cvt_hilo(v.x, v.y, h2, l2);
        ((uint32_t*)(smem + OFF_EH))[b * (SB / 2) + h] = h2;
        ((uint32_t*)(smem + OFF_EL))[b * (SB / 2) + h] = l2;
    }
    if (tid < 64) rs_s[tid] = 0.0f;

    float rsacc[8];
#pragma unroll
    for (int j = 0; j < 8; j++) rsacc[j] = 0.0f;

    for (int tile = blockIdx.x; tile < ntiles; tile += gridDim.x) {
        const int p0 = tile * 64;
        // stage Bm tile (native [p][k])
        for (int idx = tid; idx < 64 * (KPAD / 2); idx += 256) {
            int pr = idx / (KPAD / 2), h = idx % (KPAD / 2), k = 2 * h, p = p0 + pr;
            float2 v = make_float2(0.f, 0.f);
            if (p < numP && k < KG) v = *(const float2*)&Bm[(size_t)p * KG + k];
            uint32_t h2, l2; cvt_hilo(v.x, v.y, h2, l2);
            ((uint32_t*)(smem + OFF_BH))[pr * (SB / 2) + h] = h2;
            ((uint32_t*)(smem + OFF_BL))[pr * (SB / 2) + h] = l2;
        }
        if (tid < 64) colsum[tid] = 0.0f;
        __syncthreads();

        float acc[4][4];
#pragma unroll
        for (int t = 0; t < 4; t++)
#pragma unroll
            for (int i = 0; i < 4; i++) acc[t][i] = 0.0f;

#pragma unroll
        for (int kk = 0; kk < KK; kk++) {
            uint32_t ah[4], al[4];
            uint32_t ra = (uint32_t)((wr * 16 + (lane & 15)) * (SB * 2) + kk * 32 + (lane >> 4) * 16);
            LDSM_X4(ah, sb32 + OFF_BH + ra);
            LDSM_X4(al, sb32 + OFF_BL + ra);
#pragma unroll
            for (int g = 0; g < 2; g++) {
                uint32_t rb = (uint32_t)((wc * 32 + g * 16 + (lane & 15)) * (SB * 2) + kk * 32 + (lane >> 4) * 16);
                uint32_t eh[4], el[4];
                LDSM_X4(eh, sb32 + OFF_EH + rb);
                LDSM_X4(el, sb32 + OFF_EL + rb);
                // n-tile 2g: {r0, r2}; n-tile 2g+1: {r1, r3}
                MMA16816(acc[2 * g],     ah, eh[0], eh[2]);
                MMA16816(acc[2 * g],     al, eh[0], eh[2]);
                MMA16816(acc[2 * g],     ah, el[0], el[2]);
                MMA16816(acc[2 * g + 1], ah, eh[1], eh[3]);
                MMA16816(acc[2 * g + 1], al, eh[1], eh[3]);
                MMA16816(acc[2 * g + 1], ah, el[1], el[3]);
            }
        }

        // epilogue
        const int m0 = wr * 16 + (lane >> 2), m1 = m0 + 8;
        const int pA = p0 + m0, pB = p0 + m1;
        const bool vA = pA < numP, vB = pB < numP;
        const size_t gA = (size_t)(pbase + pA), gB = (size_t)(pbase + pB);
        float cs0 = 0.f, cs1 = 0.f;
#pragma unroll
        for (int t = 0; t < 4; t++) {
            const int b = wc * 32 + t * 8 + (lane & 3) * 2;
            {
                float gv0 = vA ? G[(size_t)b * TOTP + gA] : 0.f;
                float gv1 = vA ? G[(size_t)(b + 1) * TOTP + gA] : 0.f;
                float r0 = gv0 - acc[t][0], r1 = gv1 - acc[t][1];
                if (vA) {
                    g_resid[(size_t)b * TOTP + gA] = r0;
                    g_resid[(size_t)(b + 1) * TOTP + gA] = r1;
                }
                rsacc[2 * t] += r0 * r0; rsacc[2 * t + 1] += r1 * r1;
                cs0 += gv0 + gv1;
            }
            {
                float gv0 = vB ? G[(size_t)b * TOTP + gB] : 0.f;
                float gv1 = vB ? G[(size_t)(b + 1) * TOTP + gB] : 0.f;
                float r0 = gv0 - acc[t][2], r1 = gv1 - acc[t][3];
                if (vB) {
                    g_resid[(size_t)b * TOTP + gB] = r0;
                    g_resid[(size_t)(b + 1) * TOTP + gB] = r1;
                }
                rsacc[2 * t] += r0 * r0; rsacc[2 * t + 1] += r1 * r1;
                cs1 += gv0 + gv1;
            }
        }
        cs0 += __shfl_xor_sync(~0u, cs0, 1); cs0 += __shfl_xor_sync(~0u, cs0, 2);
        cs1 += __shfl_xor_sync(~0u, cs1, 1); cs1 += __shfl_xor_sync(~0u, cs1, 2);
        if ((lane & 3) == 0) {
            atomicAdd(&colsum[m0], cs0);
            atomicAdd(&colsum[m1], cs1);
        }
        __syncthreads();
        if (tid < 64) {
            int p = p0 + tid;
            if (p < numP) out_tg[p] = colsum[tid] * (1.0f / BATCH);
        }
        __syncthreads();
    }

    // rsq reduction: sum over lanes with same (lane&3)
#pragma unroll
    for (int j = 0; j < 8; j++) {
        float v = rsacc[j];
        v += __shfl_xor_sync(~0u, v, 4);
        v += __shfl_xor_sync(~0u, v, 8);
        v += __shfl_xor_sync(~0u, v, 16);
        rsacc[j] = v;
    }
    if (lane < 4) {
#pragma unroll
        for (int t = 0; t < 4; t++) {
            atomicAdd(&rs_s[wc * 32 + t * 8 + lane * 2],     rsacc[2 * t]);
            atomicAdd(&rs_s[wc * 32 + t * 8 + lane * 2 + 1], rsacc[2 * t + 1]);
        }
    }
    __syncthreads();
    if (tid < 64) atomicAdd(&g_rsq[tid], rs_s[tid]);
}

// ---------------- launch ----------------
extern "C" void kernel_launch(void* const* d_in, const int* in_sizes, int n_in,
                              void* d_out, int out_size) {
    (void)in_sizes; (void)n_in; (void)out_size;
    const float* G  = (const float*)d_in[0];
    const float* B0 = (const float*)d_in[1];
    const float* B1 = (const float*)d_in[2];
    const float* B2 = (const float*)d_in[3];
    float* out = (float*)d_out;

    static bool attr_done = false;
    if (!attr_done) {
        cudaFuncSetAttribute(k_gemm1_mma<104,128>, cudaFuncAttributeMaxDynamicSharedMemorySize, 53248);
        cudaFuncSetAttribute(k_gemm1_mma<156,160>, cudaFuncAttributeMaxDynamicSharedMemorySize, 61440);
        cudaFuncSetAttribute(k_gemm1_mma<138,160>, cudaFuncAttributeMaxDynamicSharedMemorySize, 61440);
        cudaFuncSetAttribute(k_gemm2_mma<104,112>, cudaFuncAttributeMaxDynamicSharedMemorySize, 61952);
        cudaFuncSetAttribute(k_gemm2_mma<156,160>, cudaFuncAttributeMaxDynamicSharedMemorySize, 86528);
        cudaFuncSetAttribute(k_gemm2_mma<138,144>, cudaFuncAttributeMaxDynamicSharedMemorySize, 78336);
        attr_done = true;
    }

    k_init<<<100, 256>>>();

    k_gemm1_mma<104,128><<<261, 256, 53248>>>(G, B0, 100000,      0,   0, 384);
    k_gemm1_mma<156,160><<<293, 256, 61440>>>(G, B1, 225000, 100000, 104, 768);
    k_gemm1_mma<138,160><<<274, 256, 61440>>>(G, B2, 175000, 325000, 260, 640);

    k_embed<<<1, 256>>>(out);

    float* out_tg = out + 398 + TOTP;
    k_gemm2_mma<104,112><<<296, 256, 61952>>>(G, B0, out_tg,          100000,      0,   0, 1563);
    k_gemm2_mma<156,160><<<296, 256, 86528>>>(G, B1, out_tg + 100000, 225000, 100000, 104, 3516);
    k_gemm2_mma<138,144><<<296, 256, 78336>>>(G, B2, out_tg + 325000, 175000, 325000, 260, 2735);

    k_final<<<(TOTP / 4 + 255) / 256, 256>>>(out + 398);
}

// round 7
// speedup vs baseline: 2.3466x; 1.3700x over previous
#include <cuda_runtime.h>
#include <cuda_bf16.h>
#include <cstdint>
#include <math.h>

#define TOTP 500000
#define BATCH 64
#define KTOT 398
#define CLIP0 1.0f
#define CLIP1 1.0f

__device__ float g_E[BATCH * KTOT];
__device__ float g_rsq[BATCH];
__device__ __align__(16) float g_resid[(size_t)BATCH * TOTP];

// ---------------- helpers ----------------
__device__ __forceinline__ uint32_t smem_u32(const void* p) {
    uint32_t a;
    asm("{ .reg .u64 t; cvta.to.shared.u64 t, %1; cvt.u32.u64 %0, t; }" : "=r"(a) : "l"(p));
    return a;
}
// split-bf16: hi = truncated bf16 pair, lo = rn bf16 of remainder pair.
__device__ __forceinline__ void cvt_hilo(float x, float y, uint32_t& hi2, uint32_t& lo2) {
    uint32_t ux = __float_as_uint(x), uy = __float_as_uint(y);
    hi2 = __byte_perm(ux, uy, 0x7632);
    float lx = x - __uint_as_float(ux & 0xFFFF0000u);
    float ly = y - __uint_as_float(uy & 0xFFFF0000u);
    asm("cvt.rn.bf16x2.f32 %0, %1, %2;" : "=r"(lo2) : "f"(ly), "f"(lx));
}
#define LDSM_X4(r, a) \
    asm volatile("ldmatrix.sync.aligned.m8n8.x4.shared.b16 {%0,%1,%2,%3}, [%4];" \
        : "=r"((r)[0]), "=r"((r)[1]), "=r"((r)[2]), "=r"((r)[3]) : "r"(a))
#define LDSM_X4T(r, a) \
    asm volatile("ldmatrix.sync.aligned.m8n8.x4.trans.shared.b16 {%0,%1,%2,%3}, [%4];" \
        : "=r"((r)[0]), "=r"((r)[1]), "=r"((r)[2]), "=r"((r)[3]) : "r"(a))
#define MMA16816(d, a, b0, b1) \
    asm volatile("mma.sync.aligned.m16n8k16.row.col.f32.bf16.bf16.f32 " \
        "{%0,%1,%2,%3}, {%4,%5,%6,%7}, {%8,%9}, {%0,%1,%2,%3};" \
        : "+f"((d)[0]), "+f"((d)[1]), "+f"((d)[2]), "+f"((d)[3]) \
        : "r"((a)[0]), "r"((a)[1]), "r"((a)[2]), "r"((a)[3]), "r"(b0), "r"(b1))

// ---------------- small kernels ----------------
__global__ void k_init(float* __restrict__ out_tg) {
    const int i = blockIdx.x * blockDim.x + threadIdx.x;
    const int stride = gridDim.x * blockDim.x;
    for (int t = i; t < TOTP; t += stride) out_tg[t] = 0.0f;
    if (i < BATCH * KTOT) g_E[i] = 0.0f;
    if (i < BATCH) g_rsq[i] = 0.0f;
}

__global__ void k_embed(float* __restrict__ out) {
    __shared__ float scale[BATCH];
    const int tid = threadIdx.x;
    if (tid < BATCH) {
        float s = 0.0f;
        for (int j = 0; j < KTOT; j++) { float v = g_E[tid * KTOT + j]; s += v * v; }
        float n = sqrtf(s);
        scale[tid] = ((n > CLIP0) ? (CLIP0 / n) : 1.0f) * (1.0f / BATCH);
    }
    __syncthreads();
    for (int j = tid; j < KTOT; j += blockDim.x) {
        float s = 0.0f;
        for (int b = 0; b < BATCH; b++) s += g_E[b * KTOT + j] * scale[b];
        out[j] = s;
    }
}

__global__ __launch_bounds__(256) void k_final(float* __restrict__ out_resid) {
    __shared__ float scale[BATCH];
    const int tid = threadIdx.x;
    if (tid < BATCH) {
        float n = sqrtf(g_rsq[tid]);
        scale[tid] = ((n > CLIP1) ? (CLIP1 / n) : 1.0f) * (1.0f / BATCH);
    }
    __syncthreads();
    const int p4 = blockIdx.x * blockDim.x + tid;
    if (p4 < TOTP / 4) {
        float4 s = make_float4(0.f, 0.f, 0.f, 0.f);
#pragma unroll 4
        for (int b = 0; b < BATCH; b++) {
            float4 r = *(const float4*)&g_resid[(size_t)b * TOTP + p4 * 4];
            float sc = scale[b];
            s.x += r.x * sc; s.y += r.y * sc; s.z += r.z * sc; s.w += r.w * sc;
        }
        *(float2*)&out_resid[p4 * 4]     = make_float2(s.x, s.y);
        *(float2*)&out_resid[p4 * 4 + 2] = make_float2(s.z, s.w);
    }
}

// =============== GEMM1 (HMMA, pipelined): E[b][c] += sum_p G[b][p]*Bm[p][c] ===============
// M=64(batch), N=NPAD, k-step 32 (split-K chunks). 8 warps = 4(m16) x 2(n NPAD/2).
// Register-prefetch pipeline: LDG(s+1) | MMA(s) | sync | STS(s+1) | sync.
template <int KG, int NPAD>
__global__ __launch_bounds__(256, 2) void k_gemm1_mma(
    const float* __restrict__ G, const float* __restrict__ Bm,
    int numP, int pbase, int koff, int chunk)
{
    constexpr int NH = NPAD / 2, NT = NH / 8, NG = NT / 2;
    constexpr int SBH = NPAD + 8;          // B row stride (halfwords); *2B mult of 16
    constexpr int GSTR = 20;               // G row stride (u32) = 80B, conflict-free
    constexpr int BN = NPAD / 16;          // float2 per thread for B stage
    constexpr int OFF_GH = 0;
    constexpr int OFF_GL = 64 * GSTR * 4;
    constexpr int OFF_BH = 2 * 64 * GSTR * 4;
    constexpr int BSZ = 32 * SBH * 2;
    constexpr int OFF_BL = OFF_BH + BSZ;

    extern __shared__ __align__(16) char smem[];
    const uint32_t sb32 = smem_u32(smem);
    const int tid = threadIdx.x, wid = tid >> 5, lane = tid & 31;
    const int wr = wid >> 1, wc = wid & 1;

    const int pstart = blockIdx.x * chunk;
    const int pend = min(pstart + chunk, numP);
    const int nsteps = (pend - pstart + 31) >> 5;

    float2 gpre[4];
    float2 bpre[BN];

    auto ldg_step = [&](int pt) {
#pragma unroll
        for (int j = 0; j < 4; j++) {
            int idx = tid + j * 256;
            int b = idx >> 4, pp = idx & 15, p = pt + 2 * pp;
            gpre[j] = (p < pend) ? *(const float2*)&G[(size_t)b * TOTP + pbase + p]
                                 : make_float2(0.f, 0.f);
        }
#pragma unroll
        for (int j = 0; j < BN; j++) {
            int idx = tid + j * 256;
            int k = idx / NH, h = idx % NH, c = 2 * h, p = pt + k;
            bpre[j] = (p < pend && c < KG) ? *(const float2*)&Bm[(size_t)p * KG + c]
                                           : make_float2(0.f, 0.f);
        }
    };
    auto sts_step = [&]() {
#pragma unroll
        for (int j = 0; j < 4; j++) {
            int idx = tid + j * 256;
            int b = idx >> 4, pp = idx & 15;
            uint32_t h2, l2; cvt_hilo(gpre[j].x, gpre[j].y, h2, l2);
            ((uint32_t*)(smem + OFF_GH))[b * GSTR + pp] = h2;
            ((uint32_t*)(smem + OFF_GL))[b * GSTR + pp] = l2;
        }
#pragma unroll
        for (int j = 0; j < BN; j++) {
            int idx = tid + j * 256;
            int k = idx / NH, h = idx % NH;
            uint32_t h2, l2; cvt_hilo(bpre[j].x, bpre[j].y, h2, l2);
            ((uint32_t*)(smem + OFF_BH))[k * (SBH / 2) + h] = h2;
            ((uint32_t*)(smem + OFF_BL))[k * (SBH / 2) + h] = l2;
        }
    };

    float acc[NT][4];
#pragma unroll
    for (int t = 0; t < NT; t++)
#pragma unroll
        for (int i = 0; i < 4; i++) acc[t][i] = 0.0f;

    // prologue
    ldg_step(pstart);
    sts_step();
    __syncthreads();

    for (int s = 0; s < nsteps; s++) {
        if (s + 1 < nsteps) ldg_step(pstart + (s + 1) * 32);
#pragma unroll
        for (int kk = 0; kk < 2; kk++) {
            uint32_t ah[4], al[4];
            uint32_t ra = (uint32_t)((wr * 16 + (lane & 15)) * 80 + kk * 32 + (lane >> 4) * 16);
            LDSM_X4(ah, sb32 + OFF_GH + ra);
            LDSM_X4(al, sb32 + OFF_GL + ra);
            uint32_t rb = (uint32_t)((kk * 16 + (lane & 15)) * (SBH * 2));
#pragma unroll
            for (int g = 0; g < NG; g++) {
                uint32_t cb = (uint32_t)((wc * NH + g * 16 + (lane >> 4) * 8) * 2);
                uint32_t bh[4], bl[4];
                LDSM_X4T(bh, sb32 + OFF_BH + rb + cb);
                LDSM_X4T(bl, sb32 + OFF_BL + rb + cb);
                MMA16816(acc[2 * g],     ah, bh[0], bh[1]);
                MMA16816(acc[2 * g],     al, bh[0], bh[1]);
                MMA16816(acc[2 * g],     ah, bl[0], bl[1]);
                MMA16816(acc[2 * g + 1], ah, bh[2], bh[3]);
                MMA16816(acc[2 * g + 1], al, bh[2], bh[3]);
                MMA16816(acc[2 * g + 1], ah, bl[2], bl[3]);
            }
        }
        __syncthreads();
        if (s + 1 < nsteps) { sts_step(); }
        __syncthreads();
    }

    // epilogue: atomic accumulate into g_E
    const int m0 = wr * 16 + (lane >> 2);
#pragma unroll
    for (int t = 0; t < NT; t++) {
        int n0 = wc * NH + t * 8 + (lane & 3) * 2;
        if (n0 < KG) {
            atomicAdd(&g_E[m0 * KTOT + koff + n0], acc[t][0]);
            atomicAdd(&g_E[(m0 + 8) * KTOT + koff + n0], acc[t][2]);
        }
        if (n0 + 1 < KG) {
            atomicAdd(&g_E[m0 * KTOT + koff + n0 + 1], acc[t][1]);
            atomicAdd(&g_E[(m0 + 8) * KTOT + koff + n0 + 1], acc[t][3]);
        }
    }
}

// =============== GEMM2 (HMMA, pipelined persistent): D[p][b] = sum_k Bm[p][k]*E[b][k] ======
// M = p-tile 64, N = 64(batch). Prefetch next Bm tile + current G epilogue into regs.
template <int KG, int KPAD>
__global__ __launch_bounds__(256, 2) void k_gemm2_mma(
    const float* __restrict__ G, const float* __restrict__ Bm,
    float* __restrict__ out_tg, int numP, int pbase, int koff, int ntiles)
{
    constexpr int SBH = KPAD + 8;
    constexpr int KK = KPAD / 16;
    constexpr int ES = 64 * SBH * 2;
    constexpr int BN = KPAD / 8;           // float2 per thread for Bm stage
    constexpr int OFF_EH = 0, OFF_EL = ES, OFF_BH = 2 * ES, OFF_BL = 3 * ES;
    constexpr int OFF_RS = 4 * ES;

    extern __shared__ __align__(16) char smem[];
    const uint32_t sb32 = smem_u32(smem);
    float* rs_s = (float*)(smem + OFF_RS);
    const int tid = threadIdx.x, wid = tid >> 5, lane = tid & 31;
    const int wr = wid >> 1, wc = wid & 1;

    // stage E (hi/lo) once; zero rs_s
    for (int idx = tid; idx < 64 * (KPAD / 2); idx += 256) {
        int b = idx / (KPAD / 2), h = idx % (KPAD / 2), k = 2 * h;
        float2 v = make_float2(0.f, 0.f);
        if (k < KG) v = *(const float2*)&g_E[b * KTOT + koff + k];
        uint32_t h2, l2; cvt_hilo(v.x, v.y, h2, l2);
        ((uint32_t*)(smem + OFF_EH))[b * (SBH / 2) + h] = h2;
        ((uint32_t*)(smem + OFF_EL))[b * (SBH / 2) + h] = l2;
    }
    if (tid < 64) rs_s[tid] = 0.0f;

    const int m0 = wr * 16 + (lane >> 2), m1 = m0 + 8;

    float2 bpre[BN];
    float gpre[16];
    float rsacc[8];
#pragma unroll
    for (int j = 0; j < 8; j++) rsacc[j] = 0.0f;

    auto ldg_bm = [&](int p0) {
#pragma unroll
        for (int j = 0; j < BN; j++) {
            int idx = tid + j * 256;
            int pr = idx / (KPAD / 2), h = idx % (KPAD / 2), k = 2 * h, p = p0 + pr;
            bpre[j] = (p < numP && k < KG) ? *(const float2*)&Bm[(size_t)p * KG + k]
                                           : make_float2(0.f, 0.f);
        }
    };
    auto sts_bm = [&]() {
#pragma unroll
        for (int j = 0; j < BN; j++) {
            int idx = tid + j * 256;
            int pr = idx / (KPAD / 2), h = idx % (KPAD / 2);
            uint32_t h2, l2; cvt_hilo(bpre[j].x, bpre[j].y, h2, l2);
            ((uint32_t*)(smem + OFF_BH))[pr * (SBH / 2) + h] = h2;
            ((uint32_t*)(smem + OFF_BL))[pr * (SBH / 2) + h] = l2;
        }
    };
    auto ldg_g = [&](int p0) {
        const int pA = p0 + m0, pB = p0 + m1;
        const bool vA = pA < numP, vB = pB < numP;
        const size_t gA = (size_t)(pbase + pA), gB = (size_t)(pbase + pB);
#pragma unroll
        for (int t = 0; t < 4; t++) {
            int b = wc * 32 + t * 8 + (lane & 3) * 2;
            gpre[4 * t + 0] = vA ? G[(size_t)b * TOTP + gA] : 0.f;
            gpre[4 * t + 1] = vA ? G[(size_t)(b + 1) * TOTP + gA] : 0.f;
            gpre[4 * t + 2] = vB ? G[(size_t)b * TOTP + gB] : 0.f;
            gpre[4 * t + 3] = vB ? G[(size_t)(b + 1) * TOTP + gB] : 0.f;
        }
    };

    // prologue: stage first tile
    int tile = blockIdx.x;
    ldg_bm(tile * 64);
    sts_bm();
    __syncthreads();

    while (tile < ntiles) {
        const int p0 = tile * 64;
        const int tn = tile + gridDim.x;
        if (tn < ntiles) ldg_bm(tn * 64);
        ldg_g(p0);

        float acc[4][4];
#pragma unroll
        for (int t = 0; t < 4; t++)
#pragma unroll
            for (int i = 0; i < 4; i++) acc[t][i] = 0.0f;

#pragma unroll
        for (int kk = 0; kk < KK; kk++) {
            uint32_t ah[4], al[4];
            uint32_t ra = (uint32_t)((wr * 16 + (lane & 15)) * (SBH * 2) + kk * 32 + (lane >> 4) * 16);
            LDSM_X4(ah, sb32 + OFF_BH + ra);
            LDSM_X4(al, sb32 + OFF_BL + ra);
#pragma unroll
            for (int g = 0; g < 2; g++) {
                uint32_t rb = (uint32_t)((wc * 32 + g * 16 + (lane & 15)) * (SBH * 2) + kk * 32 + (lane >> 4) * 16);
                uint32_t eh[4], el[4];
                LDSM_X4(eh, sb32 + OFF_EH + rb);
                LDSM_X4(el, sb32 + OFF_EL + rb);
                MMA16816(acc[2 * g],     ah, eh[0], eh[2]);
                MMA16816(acc[2 * g],     al, eh[0], eh[2]);
                MMA16816(acc[2 * g],     ah, el[0], el[2]);
                MMA16816(acc[2 * g + 1], ah, eh[1], eh[3]);
                MMA16816(acc[2 * g + 1], al, eh[1], eh[3]);
                MMA16816(acc[2 * g + 1], ah, el[1], el[3]);
            }
        }

        // epilogue (register G values; no smem)
        const int pA = p0 + m0, pB = p0 + m1;
        const bool vA = pA < numP, vB = pB < numP;
        const size_t gA = (size_t)(pbase + pA), gB = (size_t)(pbase + pB);
        float cs0 = 0.f, cs1 = 0.f;
#pragma unroll
        for (int t = 0; t < 4; t++) {
            const int b = wc * 32 + t * 8 + (lane & 3) * 2;
            {
                float gv0 = gpre[4 * t + 0], gv1 = gpre[4 * t + 1];
                float r0 = gv0 - acc[t][0], r1 = gv1 - acc[t][1];
                if (vA) {
                    g_resid[(size_t)b * TOTP + gA] = r0;
                    g_resid[(size_t)(b + 1) * TOTP + gA] = r1;
                }
                rsacc[2 * t] += r0 * r0; rsacc[2 * t + 1] += r1 * r1;
                cs0 += gv0 + gv1;
            }
            {
                float gv0 = gpre[4 * t + 2], gv1 = gpre[4 * t + 3];
                float r0 = gv0 - acc[t][2], r1 = gv1 - acc[t][3];
                if (vB) {
                    g_resid[(size_t)b * TOTP + gB] = r0;
                    g_resid[(size_t)(b + 1) * TOTP + gB] = r1;
                }
                rsacc[2 * t] += r0 * r0; rsacc[2 * t + 1] += r1 * r1;
                cs1 += gv0 + gv1;
            }
        }
        cs0 += __shfl_xor_sync(~0u, cs0, 1); cs0 += __shfl_xor_sync(~0u, cs0, 2);
        cs1 += __shfl_xor_sync(~0u, cs1, 1); cs1 += __shfl_xor_sync(~0u, cs1, 2);
        if ((lane & 3) == 0) {
            if (vA) atomicAdd(&out_tg[pA], cs0 * (1.0f / BATCH));
            if (vB) atomicAdd(&out_tg[pB], cs1 * (1.0f / BATCH));
        }

        __syncthreads();
        if (tn < ntiles) sts_bm();
        __syncthreads();
        tile = tn;
    }

    // rsq reduction: sum over lanes with same (lane&3)
#pragma unroll
    for (int j = 0; j < 8; j++) {
        float v = rsacc[j];
        v += __shfl_xor_sync(~0u, v, 4);
        v += __shfl_xor_sync(~0u, v, 8);
        v += __shfl_xor_sync(~0u, v, 16);
        rsacc[j] = v;
    }
    if (lane < 4) {
#pragma unroll
        for (int t = 0; t < 4; t++) {
            atomicAdd(&rs_s[wc * 32 + t * 8 + lane * 2],     rsacc[2 * t]);
            atomicAdd(&rs_s[wc * 32 + t * 8 + lane * 2 + 1], rsacc[2 * t + 1]);
        }
    }
    __syncthreads();
    if (tid < 64) atomicAdd(&g_rsq[tid], rs_s[tid]);
}

// ---------------- launch ----------------
extern "C" void kernel_launch(void* const* d_in, const int* in_sizes, int n_in,
                              void* d_out, int out_size) {
    (void)in_sizes; (void)n_in; (void)out_size;
    const float* G  = (const float*)d_in[0];
    const float* B0 = (const float*)d_in[1];
    const float* B1 = (const float*)d_in[2];
    const float* B2 = (const float*)d_in[3];
    float* out = (float*)d_out;
    float* out_tg = out + 398 + TOTP;

    static bool attr_done = false;
    if (!attr_done) {
        cudaFuncSetAttribute(k_gemm2_mma<104,112>, cudaFuncAttributeMaxDynamicSharedMemorySize, 61696);
        cudaFuncSetAttribute(k_gemm2_mma<156,160>, cudaFuncAttributeMaxDynamicSharedMemorySize, 86272);
        cudaFuncSetAttribute(k_gemm2_mma<138,144>, cudaFuncAttributeMaxDynamicSharedMemorySize, 78080);
        attr_done = true;
    }

    k_init<<<100, 256>>>(out_tg);

    // gemm1 smem: OFF_BH(10240) + 2*32*(NPAD+8)*2
    k_gemm1_mma<104,128><<<261, 256, 27648>>>(G, B0, 100000,      0,   0, 384);
    k_gemm1_mma<156,160><<<293, 256, 31744>>>(G, B1, 225000, 100000, 104, 768);
    k_gemm1_mma<138,160><<<274, 256, 31744>>>(G, B2, 175000, 325000, 260, 640);

    k_embed<<<1, 256>>>(out);

    k_gemm2_mma<104,112><<<296, 256, 61696>>>(G, B0, out_tg,          100000,      0,   0, 1563);
    k_gemm2_mma<156,160><<<296, 256, 86272>>>(G, B1, out_tg + 100000, 225000, 100000, 104, 3516);
    k_gemm2_mma<138,144><<<296, 256, 78080>>>(G, B2, out_tg + 325000, 175000, 325000, 260, 2735);

    k_final<<<(TOTP / 4 + 255) / 256, 256>>>(out + 398);
}

// round 8
// speedup vs baseline: 2.5992x; 1.1077x over previous
#include <cuda_runtime.h>
#include <cuda_fp16.h>
#include <cstdint>
#include <math.h>

#define TOTP 500000
#define BATCH 64
#define KTOT 398
#define CLIP0 1.0f
#define CLIP1 1.0f

__device__ float g_E[BATCH * KTOT];
__device__ float g_rsq[BATCH];
__device__ __align__(16) float g_resid[(size_t)BATCH * TOTP];

// ---------------- helpers ----------------
__device__ __forceinline__ uint32_t smem_u32(const void* p) {
    uint32_t a;
    asm("{ .reg .u64 t; cvta.to.shared.u64 t, %1; cvt.u32.u64 %0, t; }" : "=r"(a) : "l"(p));
    return a;
}
// fp16 split: hi = rn16 pair, lo = rn16 of remainder pair (lower half = x)
__device__ __forceinline__ void cvt_hilo16(float x, float y, uint32_t& hi2, uint32_t& lo2) {
    __half2 h = __floats2half2_rn(x, y);
    hi2 = *(uint32_t*)&h;
    float2 hf = __half22float2(h);
    __half2 l = __floats2half2_rn(x - hf.x, y - hf.y);
    lo2 = *(uint32_t*)&l;
}
// single fp16 pair
__device__ __forceinline__ uint32_t cvt_h16(float x, float y) {
    __half2 h = __floats2half2_rn(x, y);
    return *(uint32_t*)&h;
}
#define LDSM_X4(r, a) \
    asm volatile("ldmatrix.sync.aligned.m8n8.x4.shared.b16 {%0,%1,%2,%3}, [%4];" \
        : "=r"((r)[0]), "=r"((r)[1]), "=r"((r)[2]), "=r"((r)[3]) : "r"(a))
#define LDSM_X4T(r, a) \
    asm volatile("ldmatrix.sync.aligned.m8n8.x4.trans.shared.b16 {%0,%1,%2,%3}, [%4];" \
        : "=r"((r)[0]), "=r"((r)[1]), "=r"((r)[2]), "=r"((r)[3]) : "r"(a))
#define MMA16816(d, a, b0, b1) \
    asm volatile("mma.sync.aligned.m16n8k16.row.col.f32.f16.f16.f32 " \
        "{%0,%1,%2,%3}, {%4,%5,%6,%7}, {%8,%9}, {%0,%1,%2,%3};" \
        : "+f"((d)[0]), "+f"((d)[1]), "+f"((d)[2]), "+f"((d)[3]) \
        : "r"((a)[0]), "r"((a)[1]), "r"((a)[2]), "r"((a)[3]), "r"(b0), "r"(b1))

// ---------------- small kernels ----------------
__global__ void k_init(float* __restrict__ out_tg) {
    const int i = blockIdx.x * blockDim.x + threadIdx.x;
    const int stride = gridDim.x * blockDim.x;
    for (int t = i; t < TOTP; t += stride) out_tg[t] = 0.0f;
    if (i < BATCH * KTOT) g_E[i] = 0.0f;
    if (i < BATCH) g_rsq[i] = 0.0f;
}

__global__ void k_embed(float* __restrict__ out) {
    __shared__ float scale[BATCH];
    const int tid = threadIdx.x;
    if (tid < BATCH) {
        float s = 0.0f;
        for (int j = 0; j < KTOT; j++) { float v = g_E[tid * KTOT + j]; s += v * v; }
        float n = sqrtf(s);
        scale[tid] = ((n > CLIP0) ? (CLIP0 / n) : 1.0f) * (1.0f / BATCH);
    }
    __syncthreads();
    for (int j = tid; j < KTOT; j += blockDim.x) {
        float s = 0.0f;
        for (int b = 0; b < BATCH; b++) s += g_E[b * KTOT + j] * scale[b];
        out[j] = s;
    }
}

__global__ __launch_bounds__(256) void k_final(float* __restrict__ out_resid) {
    __shared__ float scale[BATCH];
    const int tid = threadIdx.x;
    if (tid < BATCH) {
        float n = sqrtf(g_rsq[tid]);
        scale[tid] = ((n > CLIP1) ? (CLIP1 / n) : 1.0f) * (1.0f / BATCH);
    }
    __syncthreads();
    const int p4 = blockIdx.x * blockDim.x + tid;
    if (p4 < TOTP / 4) {
        float4 s = make_float4(0.f, 0.f, 0.f, 0.f);
#pragma unroll 4
        for (int b = 0; b < BATCH; b++) {
            float4 r = *(const float4*)&g_resid[(size_t)b * TOTP + p4 * 4];
            float sc = scale[b];
            s.x += r.x * sc; s.y += r.y * sc; s.z += r.z * sc; s.w += r.w * sc;
        }
        *(float2*)&out_resid[p4 * 4]     = make_float2(s.x, s.y);
        *(float2*)&out_resid[p4 * 4 + 2] = make_float2(s.z, s.w);
    }
}

// =============== GEMM1 (fp16 HMMA, double-buffered): E[b][c] += sum_p G[b][p]*Bm[p][c] =====
// A = G split (hi+lo fp16), B = Bm single fp16. 2 MMA products. 1 sync/step.
template <int KG, int NPAD>
__global__ __launch_bounds__(256, 2) void k_gemm1_mma(
    const float* __restrict__ G, const float* __restrict__ Bm,
    int numP, int pbase, int koff, int chunk)
{
    constexpr int NH = NPAD / 2, NT = NH / 8, NG = NT / 2;
    constexpr int SBH = NPAD + 8;            // Bm row stride (halfwords)
    constexpr int GSTR = 20;                 // G row stride (u32) = 80B
    constexpr int BN = NPAD / 16;            // float2 per thread for B stage
    constexpr int GBUF = 2 * 64 * GSTR * 4;  // Gh+Gl per buffer = 10240
    constexpr int OFF_B = 2 * GBUF;          // 20480
    constexpr int BBUF = 32 * SBH * 2;

    extern __shared__ __align__(16) char smem[];
    const uint32_t sb32 = smem_u32(smem);
    const int tid = threadIdx.x, wid = tid >> 5, lane = tid & 31;
    const int wr = wid >> 1, wc = wid & 1;

    const int pstart = blockIdx.x * chunk;
    const int pend = min(pstart + chunk, numP);
    const int nsteps = (pend - pstart + 31) >> 5;

    float2 gpre[4];
    float2 bpre[BN];

    auto ldg_step = [&](int pt) {
#pragma unroll
        for (int j = 0; j < 4; j++) {
            int idx = tid + j * 256;
            int b = idx >> 4, pp = idx & 15, p = pt + 2 * pp;
            gpre[j] = (p < pend) ? *(const float2*)&G[(size_t)b * TOTP + pbase + p]
                                 : make_float2(0.f, 0.f);
        }
#pragma unroll
        for (int j = 0; j < BN; j++) {
            int idx = tid + j * 256;
            int k = idx / NH, h = idx % NH, c = 2 * h, p = pt + k;
            bpre[j] = (p < pend && c < KG) ? *(const float2*)&Bm[(size_t)p * KG + c]
                                           : make_float2(0.f, 0.f);
        }
    };
    auto sts_step = [&](int buf) {
        char* gb = smem + buf * GBUF;
        char* bb = smem + OFF_B + buf * BBUF;
#pragma unroll
        for (int j = 0; j < 4; j++) {
            int idx = tid + j * 256;
            int b = idx >> 4, pp = idx & 15;
            uint32_t h2, l2; cvt_hilo16(gpre[j].x, gpre[j].y, h2, l2);
            ((uint32_t*)gb)[b * GSTR + pp] = h2;
            ((uint32_t*)(gb + 5120))[b * GSTR + pp] = l2;
        }
#pragma unroll
        for (int j = 0; j < BN; j++) {
            int idx = tid + j * 256;
            int k = idx / NH, h = idx % NH;
            ((uint32_t*)bb)[k * (SBH / 2) + h] = cvt_h16(bpre[j].x, bpre[j].y);
        }
    };

    float acc[NT][4];
#pragma unroll
    for (int t = 0; t < NT; t++)
#pragma unroll
        for (int i = 0; i < 4; i++) acc[t][i] = 0.0f;

    // prologue
    ldg_step(pstart);
    sts_step(0);
    __syncthreads();

    for (int s = 0; s < nsteps; s++) {
        const int cur = s & 1;
        if (s + 1 < nsteps) ldg_step(pstart + (s + 1) * 32);
        const uint32_t gB = sb32 + cur * GBUF;
        const uint32_t bB = sb32 + OFF_B + cur * BBUF;
#pragma unroll
        for (int kk = 0; kk < 2; kk++) {
            uint32_t ah[4], al[4];
            uint32_t ra = (uint32_t)((wr * 16 + (lane & 15)) * 80 + kk * 32 + (lane >> 4) * 16);
            LDSM_X4(ah, gB + ra);
            LDSM_X4(al, gB + 5120 + ra);
            uint32_t rb = (uint32_t)((kk * 16 + (lane & 15)) * (SBH * 2));
#pragma unroll
            for (int g = 0; g < NG; g++) {
                uint32_t cb = (uint32_t)((wc * NH + g * 16 + (lane >> 4) * 8) * 2);
                uint32_t bh[4];
                LDSM_X4T(bh, bB + rb + cb);
                MMA16816(acc[2 * g],     ah, bh[0], bh[1]);
                MMA16816(acc[2 * g],     al, bh[0], bh[1]);
                MMA16816(acc[2 * g + 1], ah, bh[2], bh[3]);
                MMA16816(acc[2 * g + 1], al, bh[2], bh[3]);
            }
        }
        if (s + 1 < nsteps) sts_step(cur ^ 1);
        __syncthreads();
    }

    // epilogue: atomic accumulate into g_E
    const int m0 = wr * 16 + (lane >> 2);
#pragma unroll
    for (int t = 0; t < NT; t++) {
        int n0 = wc * NH + t * 8 + (lane & 3) * 2;
        if (n0 < KG) {
            atomicAdd(&g_E[m0 * KTOT + koff + n0], acc[t][0]);
            atomicAdd(&g_E[(m0 + 8) * KTOT + koff + n0], acc[t][2]);
        }
        if (n0 + 1 < KG) {
            atomicAdd(&g_E[m0 * KTOT + koff + n0 + 1], acc[t][1]);
            atomicAdd(&g_E[(m0 + 8) * KTOT + koff + n0 + 1], acc[t][3]);
        }
    }
}

// =============== GEMM2 (fp16 HMMA, double-buffered persistent): D[p][b] = sum_k Bm[p][k]*E[b][k]
// A = Bm single fp16 (double-buffered); B = E split hi+lo (resident). 2 MMA products.
template <int KG, int KPAD>
__global__ __launch_bounds__(256, 2) void k_gemm2_mma(
    const float* __restrict__ G, const float* __restrict__ Bm,
    float* __restrict__ out_tg, int numP, int pbase, int koff, int ntiles)
{
    constexpr int SBH = KPAD + 8;
    constexpr int KK = KPAD / 16;
    constexpr int S2 = 64 * SBH * 2;
    constexpr int BN = KPAD / 8;            // float2 per thread for Bm stage
    constexpr int OFF_EH = 0, OFF_EL = S2, OFF_B = 2 * S2;
    constexpr int OFF_RS = 4 * S2;

    extern __shared__ __align__(16) char smem[];
    const uint32_t sb32 = smem_u32(smem);
    float* rs_s = (float*)(smem + OFF_RS);
    const int tid = threadIdx.x, wid = tid >> 5, lane = tid & 31;
    const int wr = wid >> 1, wc = wid & 1;

    // stage E (hi/lo fp16) once; zero rs_s
    for (int idx = tid; idx < 64 * (KPAD / 2); idx += 256) {
        int b = idx / (KPAD / 2), h = idx % (KPAD / 2), k = 2 * h;
        float2 v = make_float2(0.f, 0.f);
        if (k < KG) v = *(const float2*)&g_E[b * KTOT + koff + k];
        uint32_t h2, l2; cvt_hilo16(v.x, v.y, h2, l2);
        ((uint32_t*)(smem + OFF_EH))[b * (SBH / 2) + h] = h2;
        ((uint32_t*)(smem + OFF_EL))[b * (SBH / 2) + h] = l2;
    }
    if (tid < 64) rs_s[tid] = 0.0f;

    const int m0 = wr * 16 + (lane >> 2), m1 = m0 + 8;

    float2 bpre[BN];
    float gpre[16];
    float rsacc[8];
#pragma unroll
    for (int j = 0; j < 8; j++) rsacc[j] = 0.0f;

    auto ldg_bm = [&](int p0) {
#pragma unroll
        for (int j = 0; j < BN; j++) {
            int idx = tid + j * 256;
            int pr = idx / (KPAD / 2), h = idx % (KPAD / 2), k = 2 * h, p = p0 + pr;
            bpre[j] = (p < numP && k < KG) ? *(const float2*)&Bm[(size_t)p * KG + k]
                                           : make_float2(0.f, 0.f);
        }
    };
    auto sts_bm = [&](int buf) {
        char* bb = smem + OFF_B + buf * S2;
#pragma unroll
        for (int j = 0; j < BN; j++) {
            int idx = tid + j * 256;
            int pr = idx / (KPAD / 2), h = idx % (KPAD / 2);
            ((uint32_t*)bb)[pr * (SBH / 2) + h] = cvt_h16(bpre[j].x, bpre[j].y);
        }
    };
    auto ldg_g = [&](int p0) {
        const int pA = p0 + m0, pB = p0 + m1;
        const bool vA = pA < numP, vB = pB < numP;
        const size_t gA = (size_t)(pbase + pA), gB = (size_t)(pbase + pB);
#pragma unroll
        for (int t = 0; t < 4; t++) {
            int b = wc * 32 + t * 8 + (lane & 3) * 2;
            gpre[4 * t + 0] = vA ? G[(size_t)b * TOTP + gA] : 0.f;
            gpre[4 * t + 1] = vA ? G[(size_t)(b + 1) * TOTP + gA] : 0.f;
            gpre[4 * t + 2] = vB ? G[(size_t)b * TOTP + gB] : 0.f;
            gpre[4 * t + 3] = vB ? G[(size_t)(b + 1) * TOTP + gB] : 0.f;
        }
    };

    // prologue
    int tile = blockIdx.x;
    int cur = 0;
    if (tile < ntiles) { ldg_bm(tile * 64); sts_bm(0); }
    __syncthreads();

    while (tile < ntiles) {
        const int p0 = tile * 64;
        const int tn = tile + gridDim.x;
        if (tn < ntiles) ldg_bm(tn * 64);
        ldg_g(p0);

        float acc[4][4];
#pragma unroll
        for (int t = 0; t < 4; t++)
#pragma unroll
            for (int i = 0; i < 4; i++) acc[t][i] = 0.0f;

        const uint32_t bB = sb32 + OFF_B + cur * S2;
#pragma unroll
        for (int kk = 0; kk < KK; kk++) {
            uint32_t ah[4];
            uint32_t ra = (uint32_t)((wr * 16 + (lane & 15)) * (SBH * 2) + kk * 32 + (lane >> 4) * 16);
            LDSM_X4(ah, bB + ra);
#pragma unroll
            for (int g = 0; g < 2; g++) {
                uint32_t rb = (uint32_t)((wc * 32 + g * 16 + (lane & 15)) * (SBH * 2) + kk * 32 + (lane >> 4) * 16);
                uint32_t eh[4], el[4];
                LDSM_X4(eh, sb32 + OFF_EH + rb);
                LDSM_X4(el, sb32 + OFF_EL + rb);
                MMA16816(acc[2 * g],     ah, eh[0], eh[2]);
                MMA16816(acc[2 * g],     ah, el[0], el[2]);
                MMA16816(acc[2 * g + 1], ah, eh[1], eh[3]);
                MMA16816(acc[2 * g + 1], ah, el[1], el[3]);
            }
        }

        if (tn < ntiles) sts_bm(cur ^ 1);

        // epilogue (register G values)
        const int pA = p0 + m0, pB = p0 + m1;
        const bool vA = pA < numP, vB = pB < numP;
        const size_t gA = (size_t)(pbase + pA), gB = (size_t)(pbase + pB);
        float cs0 = 0.f, cs1 = 0.f;
#pragma unroll
        for (int t = 0; t < 4; t++) {
            const int b = wc * 32 + t * 8 + (lane & 3) * 2;
            {
                float gv0 = gpre[4 * t + 0], gv1 = gpre[4 * t + 1];
                float r0 = gv0 - acc[t][0], r1 = gv1 - acc[t][1];
                if (vA) {
                    g_resid[(size_t)b * TOTP + gA] = r0;
                    g_resid[(size_t)(b + 1) * TOTP + gA] = r1;
                }
                rsacc[2 * t] += r0 * r0; rsacc[2 * t + 1] += r1 * r1;
                cs0 += gv0 + gv1;
            }
            {
                float gv0 = gpre[4 * t + 2], gv1 = gpre[4 * t + 3];
                float r0 = gv0 - acc[t][2], r1 = gv1 - acc[t][3];
                if (vB) {
                    g_resid[(size_t)b * TOTP + gB] = r0;
                    g_resid[(size_t)(b + 1) * TOTP + gB] = r1;
                }
                rsacc[2 * t] += r0 * r0; rsacc[2 * t + 1] += r1 * r1;
                cs1 += gv0 + gv1;
            }
        }
        cs0 += __shfl_xor_sync(~0u, cs0, 1); cs0 += __shfl_xor_sync(~0u, cs0, 2);
        cs1 += __shfl_xor_sync(~0u, cs1, 1); cs1 += __shfl_xor_sync(~0u, cs1, 2);
        if ((lane & 3) == 0) {
            if (vA) atomicAdd(&out_tg[pA], cs0 * (1.0f / BATCH));
            if (vB) atomicAdd(&out_tg[pB], cs1 * (1.0f / BATCH));
        }

        __syncthreads();
        tile = tn;
        cur ^= 1;
    }

    // rsq reduction
#pragma unroll
    for (int j = 0; j < 8; j++) {
        float v = rsacc[j];
        v += __shfl_xor_sync(~0u, v, 4);
        v += __shfl_xor_sync(~0u, v, 8);
        v += __shfl_xor_sync(~0u, v, 16);
        rsacc[j] = v;
    }
    if (lane < 4) {
#pragma unroll
        for (int t = 0; t < 4; t++) {
            atomicAdd(&rs_s[wc * 32 + t * 8 + lane * 2],     rsacc[2 * t]);
            atomicAdd(&rs_s[wc * 32 + t * 8 + lane * 2 + 1], rsacc[2 * t + 1]);
        }
    }
    __syncthreads();
    if (tid < 64) atomicAdd(&g_rsq[tid], rs_s[tid]);
}

// ---------------- launch ----------------
extern "C" void kernel_launch(void* const* d_in, const int* in_sizes, int n_in,
                              void* d_out, int out_size) {
    (void)in_sizes; (void)n_in; (void)out_size;
    const float* G  = (const float*)d_in[0];
    const float* B0 = (const float*)d_in[1];
    const float* B1 = (const float*)d_in[2];
    const float* B2 = (const float*)d_in[3];
    float* out = (float*)d_out;
    float* out_tg = out + 398 + TOTP;

    static bool attr_done = false;
    if (!attr_done) {
        cudaFuncSetAttribute(k_gemm2_mma<104,112>, cudaFuncAttributeMaxDynamicSharedMemorySize, 61696);
        cudaFuncSetAttribute(k_gemm2_mma<156,160>, cudaFuncAttributeMaxDynamicSharedMemorySize, 86272);
        cudaFuncSetAttribute(k_gemm2_mma<138,144>, cudaFuncAttributeMaxDynamicSharedMemorySize, 78080);
        attr_done = true;
    }

    k_init<<<100, 256>>>(out_tg);

    // gemm1 smem: 20480 + 2*32*(NPAD+8)*2
    k_gemm1_mma<104,128><<<261, 256, 37888>>>(G, B0, 100000,      0,   0, 384);
    k_gemm1_mma<156,160><<<293, 256, 41984>>>(G, B1, 225000, 100000, 104, 768);
    k_gemm1_mma<138,160><<<274, 256, 41984>>>(G, B2, 175000, 325000, 260, 640);

    k_embed<<<1, 256>>>(out);

    // gemm2 smem: 4*64*(KPAD+8)*2 + 256
    k_gemm2_mma<104,112><<<296, 256, 61696>>>(G, B0, out_tg,          100000,      0,   0, 1563);
    k_gemm2_mma<156,160><<<296, 256, 86272>>>(G, B1, out_tg + 100000, 225000, 100000, 104, 3516);
    k_gemm2_mma<138,144><<<296, 256, 78080>>>(G, B2, out_tg + 325000, 175000, 325000, 260, 2735);

    k_final<<<(TOTP / 4 + 255) / 256, 256>>>(out + 398);
}

// round 9
// speedup vs baseline: 2.6974x; 1.0378x over previous
#include <cuda_runtime.h>
#include <cuda_fp16.h>
#include <cstdint>
#include <math.h>

#define TOTP 500000
#define BATCH 64
#define KTOT 398
#define CLIP0 1.0f
#define CLIP1 1.0f

__device__ float g_E[BATCH * KTOT];
__device__ float g_rsq[BATCH];
__device__ __align__(16) __half g_residH[(size_t)BATCH * TOTP];  // fp16 residual, 64MB

// ---------------- helpers ----------------
__device__ __forceinline__ uint32_t smem_u32(const void* p) {
    uint32_t a;
    asm("{ .reg .u64 t; cvta.to.shared.u64 t, %1; cvt.u32.u64 %0, t; }" : "=r"(a) : "l"(p));
    return a;
}
__device__ __forceinline__ void cvt_hilo16(float x, float y, uint32_t& hi2, uint32_t& lo2) {
    __half2 h = __floats2half2_rn(x, y);
    hi2 = *(uint32_t*)&h;
    float2 hf = __half22float2(h);
    __half2 l = __floats2half2_rn(x - hf.x, y - hf.y);
    lo2 = *(uint32_t*)&l;
}
__device__ __forceinline__ uint32_t cvt_h16(float x, float y) {
    __half2 h = __floats2half2_rn(x, y);
    return *(uint32_t*)&h;
}
#define LDSM_X4(r, a) \
    asm volatile("ldmatrix.sync.aligned.m8n8.x4.shared.b16 {%0,%1,%2,%3}, [%4];" \
        : "=r"((r)[0]), "=r"((r)[1]), "=r"((r)[2]), "=r"((r)[3]) : "r"(a))
#define LDSM_X4T(r, a) \
    asm volatile("ldmatrix.sync.aligned.m8n8.x4.trans.shared.b16 {%0,%1,%2,%3}, [%4];" \
        : "=r"((r)[0]), "=r"((r)[1]), "=r"((r)[2]), "=r"((r)[3]) : "r"(a))
#define MMA16816(d, a, b0, b1) \
    asm volatile("mma.sync.aligned.m16n8k16.row.col.f32.f16.f16.f32 " \
        "{%0,%1,%2,%3}, {%4,%5,%6,%7}, {%8,%9}, {%0,%1,%2,%3};" \
        : "+f"((d)[0]), "+f"((d)[1]), "+f"((d)[2]), "+f"((d)[3]) \
        : "r"((a)[0]), "r"((a)[1]), "r"((a)[2]), "r"((a)[3]), "r"(b0), "r"(b1))

template <int CPS>
__device__ __forceinline__ void cp_async_b(uint32_t dst, const void* src, int bytes);
template <> __device__ __forceinline__ void cp_async_b<16>(uint32_t d, const void* s, int b) {
    asm volatile("cp.async.cg.shared.global [%0], [%1], 16, %2;" :: "r"(d), "l"(s), "r"(b));
}
template <> __device__ __forceinline__ void cp_async_b<8>(uint32_t d, const void* s, int b) {
    asm volatile("cp.async.ca.shared.global [%0], [%1], 8, %2;" :: "r"(d), "l"(s), "r"(b));
}
__device__ __forceinline__ void cp_commit() { asm volatile("cp.async.commit_group;" ::: "memory"); }
__device__ __forceinline__ void cp_wait2()  { asm volatile("cp.async.wait_group 2;" ::: "memory"); }

// ---------------- small kernels ----------------
__global__ void k_init(float* __restrict__ out_tg) {
    const int i = blockIdx.x * blockDim.x + threadIdx.x;
    const int stride = gridDim.x * blockDim.x;
    for (int t = i; t < TOTP; t += stride) out_tg[t] = 0.0f;
    if (i < BATCH * KTOT) g_E[i] = 0.0f;
    if (i < BATCH) g_rsq[i] = 0.0f;
}

__global__ void k_embed(float* __restrict__ out) {
    __shared__ float scale[BATCH];
    const int tid = threadIdx.x;
    if (tid < BATCH) {
        float s = 0.0f;
        for (int j = 0; j < KTOT; j++) { float v = g_E[tid * KTOT + j]; s += v * v; }
        float n = sqrtf(s);
        scale[tid] = ((n > CLIP0) ? (CLIP0 / n) : 1.0f) * (1.0f / BATCH);
    }
    __syncthreads();
    for (int j = tid; j < KTOT; j += blockDim.x) {
        float s = 0.0f;
        for (int b = 0; b < BATCH; b++) s += g_E[b * KTOT + j] * scale[b];
        out[j] = s;
    }
}

// reads fp16 residual (8 p per thread), scales, averages
__global__ __launch_bounds__(256) void k_final(float* __restrict__ out_resid) {
    __shared__ float scale[BATCH];
    const int tid = threadIdx.x;
    if (tid < BATCH) {
        float n = sqrtf(g_rsq[tid]);
        scale[tid] = ((n > CLIP1) ? (CLIP1 / n) : 1.0f) * (1.0f / BATCH);
    }
    __syncthreads();
    const int p8 = blockIdx.x * blockDim.x + tid;
    if (p8 < TOTP / 8) {
        float s[8];
#pragma unroll
        for (int j = 0; j < 8; j++) s[j] = 0.0f;
        const size_t base = (size_t)p8 * 8;
#pragma unroll 4
        for (int b = 0; b < BATCH; b++) {
            uint4 v = *(const uint4*)(g_residH + (size_t)b * TOTP + base);
            const float sc = scale[b];
            const uint32_t* w = (const uint32_t*)&v;
#pragma unroll
            for (int q = 0; q < 4; q++) {
                float2 f = __half22float2(*(const __half2*)&w[q]);
                s[2 * q] += f.x * sc; s[2 * q + 1] += f.y * sc;
            }
        }
#pragma unroll
        for (int q = 0; q < 4; q++)
            *(float2*)&out_resid[base + 2 * q] = make_float2(s[2 * q], s[2 * q + 1]);
    }
}

// =============== GEMM1 body (fp16 HMMA, double-buffered) — unchanged core from R8 =========
template <int KG, int NPAD>
__device__ void gemm1_body(const float* __restrict__ G, const float* __restrict__ Bm,
                           int numP, int pbase, int koff, int chunk, int bid)
{
    constexpr int NH = NPAD / 2, NT = NH / 8, NG = NT / 2;
    constexpr int SBH = NPAD + 8;
    constexpr int GSTR = 20;
    constexpr int BN = NPAD / 16;
    constexpr int GBUF = 2 * 64 * GSTR * 4;
    constexpr int OFF_B = 2 * GBUF;
    constexpr int BBUF = 32 * SBH * 2;

    extern __shared__ char smem[];
    const uint32_t sb32 = smem_u32(smem);
    const int tid = threadIdx.x, wid = tid >> 5, lane = tid & 31;
    const int wr = wid >> 1, wc = wid & 1;

    const int pstart = bid * chunk;
    const int pend = min(pstart + chunk, numP);
    const int nsteps = (pend - pstart + 31) >> 5;

    float2 gpre[4];
    float2 bpre[BN];

    auto ldg_step = [&](int pt) {
#pragma unroll
        for (int j = 0; j < 4; j++) {
            int idx = tid + j * 256;
            int b = idx >> 4, pp = idx & 15, p = pt + 2 * pp;
            gpre[j] = (p < pend) ? *(const float2*)&G[(size_t)b * TOTP + pbase + p]
                                 : make_float2(0.f, 0.f);
        }
#pragma unroll
        for (int j = 0; j < BN; j++) {
            int idx = tid + j * 256;
            int k = idx / NH, h = idx % NH, c = 2 * h, p = pt + k;
            bpre[j] = (p < pend && c < KG) ? *(const float2*)&Bm[(size_t)p * KG + c]
                                           : make_float2(0.f, 0.f);
        }
    };
    auto sts_step = [&](int buf) {
        char* gb = smem + buf * GBUF;
        char* bb = smem + OFF_B + buf * BBUF;
#pragma unroll
        for (int j = 0; j < 4; j++) {
            int idx = tid + j * 256;
            int b = idx >> 4, pp = idx & 15;
            uint32_t h2, l2; cvt_hilo16(gpre[j].x, gpre[j].y, h2, l2);
            ((uint32_t*)gb)[b * GSTR + pp] = h2;
            ((uint32_t*)(gb + 5120))[b * GSTR + pp] = l2;
        }
#pragma unroll
        for (int j = 0; j < BN; j++) {
            int idx = tid + j * 256;
            int k = idx / NH, h = idx % NH;
            ((uint32_t*)bb)[k * (SBH / 2) + h] = cvt_h16(bpre[j].x, bpre[j].y);
        }
    };

    float acc[NT][4];
#pragma unroll
    for (int t = 0; t < NT; t++)
#pragma unroll
        for (int i = 0; i < 4; i++) acc[t][i] = 0.0f;

    ldg_step(pstart);
    sts_step(0);
    __syncthreads();

    for (int s = 0; s < nsteps; s++) {
        const int cur = s & 1;
        if (s + 1 < nsteps) ldg_step(pstart + (s + 1) * 32);
        const uint32_t gB = sb32 + cur * GBUF;
        const uint32_t bB = sb32 + OFF_B + cur * BBUF;
#pragma unroll
        for (int kk = 0; kk < 2; kk++) {
            uint32_t ah[4], al[4];
            uint32_t ra = (uint32_t)((wr * 16 + (lane & 15)) * 80 + kk * 32 + (lane >> 4) * 16);
            LDSM_X4(ah, gB + ra);
            LDSM_X4(al, gB + 5120 + ra);
            uint32_t rb = (uint32_t)((kk * 16 + (lane & 15)) * (SBH * 2));
#pragma unroll
            for (int g = 0; g < NG; g++) {
                uint32_t cb = (uint32_t)((wc * NH + g * 16 + (lane >> 4) * 8) * 2);
                uint32_t bh[4];
                LDSM_X4T(bh, bB + rb + cb);
                MMA16816(acc[2 * g],     ah, bh[0], bh[1]);
                MMA16816(acc[2 * g],     al, bh[0], bh[1]);
                MMA16816(acc[2 * g + 1], ah, bh[2], bh[3]);
                MMA16816(acc[2 * g + 1], al, bh[2], bh[3]);
            }
        }
        if (s + 1 < nsteps) sts_step(cur ^ 1);
        __syncthreads();
    }

    const int m0 = wr * 16 + (lane >> 2);
#pragma unroll
    for (int t = 0; t < NT; t++) {
        int n0 = wc * NH + t * 8 + (lane & 3) * 2;
        if (n0 < KG) {
            atomicAdd(&g_E[m0 * KTOT + koff + n0], acc[t][0]);
            atomicAdd(&g_E[(m0 + 8) * KTOT + koff + n0], acc[t][2]);
        }
        if (n0 + 1 < KG) {
            atomicAdd(&g_E[m0 * KTOT + koff + n0 + 1], acc[t][1]);
            atomicAdd(&g_E[(m0 + 8) * KTOT + koff + n0 + 1], acc[t][3]);
        }
    }
}

__global__ __launch_bounds__(256, 2) void k_gemm1_all(
    const float* __restrict__ G, const float* __restrict__ B0,
    const float* __restrict__ B1, const float* __restrict__ B2)
{
    const int bx = blockIdx.x;
    if (bx < 261)      gemm1_body<104,128>(G, B0, 100000,      0,   0, 384, bx);
    else if (bx < 554) gemm1_body<156,160>(G, B1, 225000, 100000, 104, 768, bx - 261);
    else               gemm1_body<138,160>(G, B2, 175000, 325000, 260, 640, bx - 554);
}

// =============== GEMM2 body: cp.async 4-stage ring, depth-2, fp16 residual ================
// D[p][b] = sum_k Bm[p][k]*E[b][k]; tiles of 64 p, k-steps of 32.
template <int KG, int KK, int CPS>
__device__ void gemm2_body(const float* __restrict__ G, const float* __restrict__ Bm,
                           float* __restrict__ out_tg, int numP, int pbase, int koff,
                           int ntiles, int cl, int NCg)
{
    constexpr int KPAD = KK * 32;
    constexpr int SBH = KPAD + 8;
    constexpr int ESZ = 64 * SBH * 2;
    constexpr int OFF_RING = 2 * ESZ;
    constexpr int SSZ = 8192;                // 64 rows x 128B
    constexpr int OFF_F16 = OFF_RING + 4 * SSZ;
    constexpr int F16S = 64 * 80;            // 64 rows x 40 halves
    constexpr int OFF_RS = OFF_F16 + 2 * F16S;
    constexpr int NCH = 128 / CPS;
    constexpr int OPT = (64 * NCH) / 256;

    extern __shared__ char smem[];
    const uint32_t sb32 = smem_u32(smem);
    float* rs_s = (float*)(smem + OFF_RS);
    const int tid = threadIdx.x, wid = tid >> 5, lane = tid & 31;
    const int wr = wid >> 1, wc = wid & 1;

    // stage E (hi/lo fp16) resident; zero rs_s
    for (int idx = tid; idx < 64 * (KPAD / 2); idx += 256) {
        int b = idx / (KPAD / 2), h = idx % (KPAD / 2), k = 2 * h;
        float2 v = make_float2(0.f, 0.f);
        if (k < KG) v = *(const float2*)&g_E[b * KTOT + koff + k];
        uint32_t h2, l2; cvt_hilo16(v.x, v.y, h2, l2);
        ((uint32_t*)smem)[b * (SBH / 2) + h] = h2;
        ((uint32_t*)(smem + ESZ))[b * (SBH / 2) + h] = l2;
    }
    if (tid < 64) rs_s[tid] = 0.0f;

    const int myT = (cl < ntiles) ? ((ntiles - cl + NCg - 1) / NCg) : 0;
    const int total = myT * KK;

    auto issue = [&](int gs) {
        if (gs >= total) return;
        const int tj = gs / KK, st = gs - tj * KK;
        const int p0 = (cl + tj * NCg) * 64;
        const int k0 = st * 32;
        const uint32_t dst0 = sb32 + OFF_RING + (gs & 3) * SSZ;
#pragma unroll
        for (int j = 0; j < OPT; j++) {
            int idx = tid + j * 256;
            int r = idx / NCH, ch = idx - r * NCH;
            int p = p0 + r;
            int rem = (p < numP) ? (KG * 4 - (k0 * 4 + ch * CPS)) : 0;
            int bytes = rem <= 0 ? 0 : (rem >= CPS ? CPS : rem);
            const char* src = (const char*)Bm + (bytes > 0 ? ((size_t)p * KG + k0) * 4 + ch * CPS : 0);
            cp_async_b<CPS>(dst0 + r * 128 + ch * CPS, src, bytes);
        }
    };
    auto cvt = [&](int gs) {
        char* stg = smem + OFF_RING + (gs & 3) * SSZ;
        char* b16 = smem + OFF_F16 + (gs & 1) * F16S;
#pragma unroll
        for (int j = 0; j < 4; j++) {
            int idx = tid + j * 256;
            int r = idx >> 4, h = idx & 15;
            float2 v = ((const float2*)(stg + r * 128))[h];
            ((uint32_t*)(b16 + r * 80))[h] = cvt_h16(v.x, v.y);
        }
    };

    const int m0 = wr * 16 + (lane >> 2), m1 = m0 + 8;
    float gpre[16];
    float acc[4][4];
    float rsacc[8];
#pragma unroll
    for (int t = 0; t < 4; t++)
#pragma unroll
        for (int i = 0; i < 4; i++) acc[t][i] = 0.0f;
#pragma unroll
    for (int j = 0; j < 8; j++) rsacc[j] = 0.0f;

    auto ldg_g = [&](int p0) {
        const int pA = p0 + m0, pB = p0 + m1;
        const bool vA = pA < numP, vB = pB < numP;
        const size_t gA = (size_t)(pbase + pA), gB = (size_t)(pbase + pB);
#pragma unroll
        for (int t = 0; t < 4; t++) {
            int b = wc * 32 + t * 8 + (lane & 3) * 2;
            gpre[4 * t + 0] = vA ? G[(size_t)b * TOTP + gA] : 0.f;
            gpre[4 * t + 1] = vA ? G[(size_t)(b + 1) * TOTP + gA] : 0.f;
            gpre[4 * t + 2] = vB ? G[(size_t)b * TOTP + gB] : 0.f;
            gpre[4 * t + 3] = vB ? G[(size_t)(b + 1) * TOTP + gB] : 0.f;
        }
    };

    // prologue: 3 stages in flight
    issue(0); cp_commit();
    issue(1); cp_commit();
    issue(2); cp_commit();
    cp_wait2();
    __syncthreads();
    if (total > 0) cvt(0);
    __syncthreads();

    int tile = cl;
    for (int gs = 0; gs < total; gs++) {
        issue(gs + 3); cp_commit();
        const int st = gs % KK;
        if (st == 0) ldg_g(tile * 64);

        // MMA from fp16 buf (current step's 32 k)
        const uint32_t aB = sb32 + OFF_F16 + (gs & 1) * F16S;
#pragma unroll
        for (int kk2 = 0; kk2 < 2; kk2++) {
            uint32_t ah[4];
            uint32_t ra = (uint32_t)((wr * 16 + (lane & 15)) * 80 + kk2 * 32 + (lane >> 4) * 16);
            LDSM_X4(ah, aB + ra);
            const int kcol = st * 32 + kk2 * 16;
#pragma unroll
            for (int g = 0; g < 2; g++) {
                uint32_t rb = (uint32_t)((wc * 32 + g * 16 + (lane & 15)) * (SBH * 2) + kcol * 2 + (lane >> 4) * 16);
                uint32_t eh[4], el[4];
                LDSM_X4(eh, sb32 + rb);
                LDSM_X4(el, sb32 + ESZ + rb);
                MMA16816(acc[2 * g],     ah, eh[0], eh[2]);
                MMA16816(acc[2 * g],     ah, el[0], el[2]);
                MMA16816(acc[2 * g + 1], ah, eh[1], eh[3]);
                MMA16816(acc[2 * g + 1], ah, el[1], el[3]);
            }
        }

        if (st == KK - 1) {
            // epilogue
            const int p0 = tile * 64;
            const int pA = p0 + m0, pB = p0 + m1;
            const bool vA = pA < numP, vB = pB < numP;
            const size_t gA = (size_t)(pbase + pA), gB = (size_t)(pbase + pB);
            float cs0 = 0.f, cs1 = 0.f;
#pragma unroll
            for (int t = 0; t < 4; t++) {
                const int b = wc * 32 + t * 8 + (lane & 3) * 2;
                {
                    float gv0 = gpre[4 * t + 0], gv1 = gpre[4 * t + 1];
                    float r0 = gv0 - acc[t][0], r1 = gv1 - acc[t][1];
                    rsacc[2 * t] += r0 * r0; rsacc[2 * t + 1] += r1 * r1;
                    cs0 += gv0 + gv1;
                    __half2 hh = __floats2half2_rn(r0, r1);
                    uint32_t cur = *(uint32_t*)&hh;
                    uint32_t oth = __shfl_xor_sync(~0u, cur, 4);
                    if (!(lane & 4) && vA) {
                        *(uint32_t*)(g_residH + (size_t)b * TOTP + gA) = __byte_perm(cur, oth, 0x5410);
                        *(uint32_t*)(g_residH + (size_t)(b + 1) * TOTP + gA) = __byte_perm(cur, oth, 0x7632);
                    }
                }
                {
                    float gv0 = gpre[4 * t + 2], gv1 = gpre[4 * t + 3];
                    float r0 = gv0 - acc[t][2], r1 = gv1 - acc[t][3];
                    rsacc[2 * t] += r0 * r0; rsacc[2 * t + 1] += r1 * r1;
                    cs1 += gv0 + gv1;
                    __half2 hh = __floats2half2_rn(r0, r1);
                    uint32_t cur = *(uint32_t*)&hh;
                    uint32_t oth = __shfl_xor_sync(~0u, cur, 4);
                    if (!(lane & 4) && vB) {
                        *(uint32_t*)(g_residH + (size_t)b * TOTP + gB) = __byte_perm(cur, oth, 0x5410);
                        *(uint32_t*)(g_residH + (size_t)(b + 1) * TOTP + gB) = __byte_perm(cur, oth, 0x7632);
                    }
                }
            }
            cs0 += __shfl_xor_sync(~0u, cs0, 1); cs0 += __shfl_xor_sync(~0u, cs0, 2);
            cs1 += __shfl_xor_sync(~0u, cs1, 1); cs1 += __shfl_xor_sync(~0u, cs1, 2);
            if ((lane & 3) == 0) {
                if (vA) atomicAdd(&out_tg[pA], cs0 * (1.0f / BATCH));
                if (vB) atomicAdd(&out_tg[pB], cs1 * (1.0f / BATCH));
            }
#pragma unroll
            for (int t = 0; t < 4; t++)
#pragma unroll
                for (int i = 0; i < 4; i++) acc[t][i] = 0.0f;
            tile += NCg;
        }

        cp_wait2();
        __syncthreads();
        if (gs + 1 < total) cvt(gs + 1);
        __syncthreads();
    }

    // rsq reduction
#pragma unroll
    for (int j = 0; j < 8; j++) {
        float v = rsacc[j];
        v += __shfl_xor_sync(~0u, v, 4);
        v += __shfl_xor_sync(~0u, v, 8);
        v += __shfl_xor_sync(~0u, v, 16);
        rsacc[j] = v;
    }
    if (lane < 4) {
#pragma unroll
        for (int t = 0; t < 4; t++) {
            atomicAdd(&rs_s[wc * 32 + t * 8 + lane * 2],     rsacc[2 * t]);
            atomicAdd(&rs_s[wc * 32 + t * 8 + lane * 2 + 1], rsacc[2 * t + 1]);
        }
    }
    __syncthreads();
    if (tid < 64) atomicAdd(&g_rsq[tid], rs_s[tid]);
}

__global__ __launch_bounds__(256, 2) void k_gemm2_all(
    const float* __restrict__ G, const float* __restrict__ B0,
    const float* __restrict__ B1, const float* __restrict__ B2,
    float* __restrict__ out_tg)
{
    const int bx = blockIdx.x;
    if (bx < 49)       gemm2_body<104,4,16>(G, B0, out_tg,          100000,      0,   0, 1563, bx,        49);
    else if (bx < 188) gemm2_body<156,5,16>(G, B1, out_tg + 100000, 225000, 100000, 104, 3516, bx - 49,  139);
    else               gemm2_body<138,5, 8>(G, B2, out_tg + 325000, 175000, 325000, 260, 2735, bx - 188, 108);
}

// ---------------- launch ----------------
extern "C" void kernel_launch(void* const* d_in, const int* in_sizes, int n_in,
                              void* d_out, int out_size) {
    (void)in_sizes; (void)n_in; (void)out_size;
    const float* G  = (const float*)d_in[0];
    const float* B0 = (const float*)d_in[1];
    const float* B1 = (const float*)d_in[2];
    const float* B2 = (const float*)d_in[3];
    float* out = (float*)d_out;
    float* out_tg = out + 398 + TOTP;

    static bool attr_done = false;
    if (!attr_done) {
        cudaFuncSetAttribute(k_gemm2_all, cudaFuncAttributeMaxDynamicSharedMemorySize, 86272);
        attr_done = true;
    }

    k_init<<<100, 256>>>(out_tg);

    k_gemm1_all<<<828, 256, 41984>>>(G, B0, B1, B2);

    k_embed<<<1, 256>>>(out);

    k_gemm2_all<<<296, 256, 86272>>>(G, B0, B1, B2, out_tg);

    k_final<<<(TOTP / 8 + 255) / 256, 256>>>(out + 398);
}

// round 10
// speedup vs baseline: 2.8496x; 1.0564x over previous
#include <cuda_runtime.h>
#include <cuda_fp16.h>
#include <cstdint>
#include <math.h>

#define TOTP 500000
#define BATCH 64
#define KTOT 398
#define CLIP0 1.0f
#define CLIP1 1.0f

__device__ float g_E[BATCH * KTOT];
__device__ float g_rsq[BATCH];
__device__ __align__(16) __half g_residH[(size_t)BATCH * TOTP];   // 64MB
// fp16 Bm copies, rows padded to 16B multiples: 104 | 160 | 144 halves per row
#define BMH_OFF1 10400000
#define BMH_OFF2 46400000
__device__ __align__(16) __half g_BmH[71600000];                  // 143MB

// ---------------- helpers ----------------
__device__ __forceinline__ uint32_t smem_u32(const void* p) {
    uint32_t a;
    asm("{ .reg .u64 t; cvta.to.shared.u64 t, %1; cvt.u32.u64 %0, t; }" : "=r"(a) : "l"(p));
    return a;
}
__device__ __forceinline__ void cvt_hilo16(float x, float y, uint32_t& hi2, uint32_t& lo2) {
    __half2 h = __floats2half2_rn(x, y);
    hi2 = *(uint32_t*)&h;
    float2 hf = __half22float2(h);
    __half2 l = __floats2half2_rn(x - hf.x, y - hf.y);
    lo2 = *(uint32_t*)&l;
}
__device__ __forceinline__ uint32_t cvt_h16(float x, float y) {
    __half2 h = __floats2half2_rn(x, y);
    return *(uint32_t*)&h;
}
#define LDSM_X4(r, a) \
    asm volatile("ldmatrix.sync.aligned.m8n8.x4.shared.b16 {%0,%1,%2,%3}, [%4];" \
        : "=r"((r)[0]), "=r"((r)[1]), "=r"((r)[2]), "=r"((r)[3]) : "r"(a))
#define LDSM_X4T(r, a) \
    asm volatile("ldmatrix.sync.aligned.m8n8.x4.trans.shared.b16 {%0,%1,%2,%3}, [%4];" \
        : "=r"((r)[0]), "=r"((r)[1]), "=r"((r)[2]), "=r"((r)[3]) : "r"(a))
#define MMA16816(d, a, b0, b1) \
    asm volatile("mma.sync.aligned.m16n8k16.row.col.f32.f16.f16.f32 " \
        "{%0,%1,%2,%3}, {%4,%5,%6,%7}, {%8,%9}, {%0,%1,%2,%3};" \
        : "+f"((d)[0]), "+f"((d)[1]), "+f"((d)[2]), "+f"((d)[3]) \
        : "r"((a)[0]), "r"((a)[1]), "r"((a)[2]), "r"((a)[3]), "r"(b0), "r"(b1))

__device__ __forceinline__ void cp_async16(uint32_t d, const void* s, int bytes) {
    asm volatile("cp.async.cg.shared.global [%0], [%1], 16, %2;" :: "r"(d), "l"(s), "r"(bytes));
}
__device__ __forceinline__ void cp_commit()  { asm volatile("cp.async.commit_group;" ::: "memory"); }
__device__ __forceinline__ void cp_wait2()   { asm volatile("cp.async.wait_group 2;" ::: "memory"); }
__device__ __forceinline__ void cp_wait0()   { asm volatile("cp.async.wait_group 0;" ::: "memory"); }

// ---------------- small kernels ----------------
__global__ void k_init(float* __restrict__ out_tg) {
    const int i = blockIdx.x * blockDim.x + threadIdx.x;
    const int stride = gridDim.x * blockDim.x;
    for (int t = i; t < TOTP; t += stride) out_tg[t] = 0.0f;
    if (i < BATCH * KTOT) g_E[i] = 0.0f;
    if (i < BATCH) g_rsq[i] = 0.0f;
}

__global__ void k_embed(float* __restrict__ out) {
    __shared__ float scale[BATCH];
    const int tid = threadIdx.x;
    if (tid < BATCH) {
        float s = 0.0f;
        for (int j = 0; j < KTOT; j++) { float v = g_E[tid * KTOT + j]; s += v * v; }
        float n = sqrtf(s);
        scale[tid] = ((n > CLIP0) ? (CLIP0 / n) : 1.0f) * (1.0f / BATCH);
    }
    __syncthreads();
    for (int j = tid; j < KTOT; j += blockDim.x) {
        float s = 0.0f;
        for (int b = 0; b < BATCH; b++) s += g_E[b * KTOT + j] * scale[b];
        out[j] = s;
    }
}

__global__ __launch_bounds__(256) void k_final(float* __restrict__ out_resid) {
    __shared__ float scale[BATCH];
    const int tid = threadIdx.x;
    if (tid < BATCH) {
        float n = sqrtf(g_rsq[tid]);
        scale[tid] = ((n > CLIP1) ? (CLIP1 / n) : 1.0f) * (1.0f / BATCH);
    }
    __syncthreads();
    const int p8 = blockIdx.x * blockDim.x + tid;
    if (p8 < TOTP / 8) {
        float s[8];
#pragma unroll
        for (int j = 0; j < 8; j++) s[j] = 0.0f;
        const size_t base = (size_t)p8 * 8;
#pragma unroll 4
        for (int b = 0; b < BATCH; b++) {
            uint4 v = *(const uint4*)(g_residH + (size_t)b * TOTP + base);
            const float sc = scale[b];
            const uint32_t* w = (const uint32_t*)&v;
#pragma unroll
            for (int q = 0; q < 4; q++) {
                float2 f = __half22float2(*(const __half2*)&w[q]);
                s[2 * q] += f.x * sc; s[2 * q + 1] += f.y * sc;
            }
        }
#pragma unroll
        for (int q = 0; q < 4; q++)
            *(float2*)&out_resid[base + 2 * q] = make_float2(s[2 * q], s[2 * q + 1]);
    }
}

// =============== GEMM1 (fp16 HMMA, double-buffered) + fp16 Bm export ======================
template <int KG, int NPAD, int KGP2>
__device__ void gemm1_body(const float* __restrict__ G, const float* __restrict__ Bm,
                           __half* __restrict__ BmH, int numP, int pbase, int koff,
                           int chunk, int bid)
{
    constexpr int NH = NPAD / 2, NT = NH / 8, NG = NT / 2;
    constexpr int SBH = NPAD + 8;
    constexpr int GSTR = 20;
    constexpr int BN = NPAD / 16;
    constexpr int GBUF = 2 * 64 * GSTR * 4;
    constexpr int OFF_B = 2 * GBUF;
    constexpr int BBUF = 32 * SBH * 2;

    extern __shared__ char smem[];
    const uint32_t sb32 = smem_u32(smem);
    const int tid = threadIdx.x, wid = tid >> 5, lane = tid & 31;
    const int wr = wid >> 1, wc = wid & 1;

    const int pstart = bid * chunk;
    const int pend = min(pstart + chunk, numP);
    const int nsteps = (pend - pstart + 31) >> 5;

    float2 gpre[4];
    float2 bpre[BN];

    auto ldg_step = [&](int pt) {
#pragma unroll
        for (int j = 0; j < 4; j++) {
            int idx = tid + j * 256;
            int b = idx >> 4, pp = idx & 15, p = pt + 2 * pp;
            gpre[j] = (p < pend) ? *(const float2*)&G[(size_t)b * TOTP + pbase + p]
                                 : make_float2(0.f, 0.f);
        }
#pragma unroll
        for (int j = 0; j < BN; j++) {
            int idx = tid + j * 256;
            int k = idx / NH, h = idx % NH, c = 2 * h, p = pt + k;
            bpre[j] = (p < pend && c < KG) ? *(const float2*)&Bm[(size_t)p * KG + c]
                                           : make_float2(0.f, 0.f);
        }
    };
    auto sts_step = [&](int buf, int pt) {
        char* gb = smem + buf * GBUF;
        char* bb = smem + OFF_B + buf * BBUF;
#pragma unroll
        for (int j = 0; j < 4; j++) {
            int idx = tid + j * 256;
            int b = idx >> 4, pp = idx & 15;
            uint32_t h2, l2; cvt_hilo16(gpre[j].x, gpre[j].y, h2, l2);
            ((uint32_t*)gb)[b * GSTR + pp] = h2;
            ((uint32_t*)(gb + 5120))[b * GSTR + pp] = l2;
        }
#pragma unroll
        for (int j = 0; j < BN; j++) {
            int idx = tid + j * 256;
            int k = idx / NH, h = idx % NH;
            uint32_t v16 = cvt_h16(bpre[j].x, bpre[j].y);
            ((uint32_t*)bb)[k * (SBH / 2) + h] = v16;
            int p = pt + k;
            if (p < pend && 2 * h < KGP2)
                *(uint32_t*)(BmH + (size_t)p * KGP2 + 2 * h) = v16;
        }
    };

    float acc[NT][4];
#pragma unroll
    for (int t = 0; t < NT; t++)
#pragma unroll
        for (int i = 0; i < 4; i++) acc[t][i] = 0.0f;

    ldg_step(pstart);
    sts_step(0, pstart);
    __syncthreads();

    for (int s = 0; s < nsteps; s++) {
        const int cur = s & 1;
        if (s + 1 < nsteps) ldg_step(pstart + (s + 1) * 32);
        const uint32_t gB = sb32 + cur * GBUF;
        const uint32_t bB = sb32 + OFF_B + cur * BBUF;
#pragma unroll
        for (int kk = 0; kk < 2; kk++) {
            uint32_t ah[4], al[4];
            uint32_t ra = (uint32_t)((wr * 16 + (lane & 15)) * 80 + kk * 32 + (lane >> 4) * 16);
            LDSM_X4(ah, gB + ra);
            LDSM_X4(al, gB + 5120 + ra);
            uint32_t rb = (uint32_t)((kk * 16 + (lane & 15)) * (SBH * 2));
#pragma unroll
            for (int g = 0; g < NG; g++) {
                uint32_t cb = (uint32_t)((wc * NH + g * 16 + (lane >> 4) * 8) * 2);
                uint32_t bh[4];
                LDSM_X4T(bh, bB + rb + cb);
                MMA16816(acc[2 * g],     ah, bh[0], bh[1]);
                MMA16816(acc[2 * g],     al, bh[0], bh[1]);
                MMA16816(acc[2 * g + 1], ah, bh[2], bh[3]);
                MMA16816(acc[2 * g + 1], al, bh[2], bh[3]);
            }
        }
        if (s + 1 < nsteps) sts_step(cur ^ 1, pstart + (s + 1) * 32);
        __syncthreads();
    }

    const int m0 = wr * 16 + (lane >> 2);
#pragma unroll
    for (int t = 0; t < NT; t++) {
        int n0 = wc * NH + t * 8 + (lane & 3) * 2;
        if (n0 < KG) {
            atomicAdd(&g_E[m0 * KTOT + koff + n0], acc[t][0]);
            atomicAdd(&g_E[(m0 + 8) * KTOT + koff + n0], acc[t][2]);
        }
        if (n0 + 1 < KG) {
            atomicAdd(&g_E[m0 * KTOT + koff + n0 + 1], acc[t][1]);
            atomicAdd(&g_E[(m0 + 8) * KTOT + koff + n0 + 1], acc[t][3]);
        }
    }
}

__global__ __launch_bounds__(256, 2) void k_gemm1_all(
    const float* __restrict__ G, const float* __restrict__ B0,
    const float* __restrict__ B1, const float* __restrict__ B2)
{
    const int bx = blockIdx.x;
    if (bx < 261)      gemm1_body<104,128,104>(G, B0, g_BmH,            100000,      0,   0, 384, bx);
    else if (bx < 554) gemm1_body<156,160,160>(G, B1, g_BmH + BMH_OFF1, 225000, 100000, 104, 768, bx - 261);
    else               gemm1_body<138,160,144>(G, B2, g_BmH + BMH_OFF2, 175000, 325000, 260, 640, bx - 554);
}

// =============== GEMM2: fp16 Bm via cp.async 4-deep ring, no cvt pass =====================
// D[p][b] = sum_k Bm[p][k]*E[b][k]; tiles of 64 p, k-steps of 32.
template <int KG, int KK, int KGP2>
__device__ void gemm2_body(const float* __restrict__ G, const __half* __restrict__ BmH,
                           float* __restrict__ out_tg, int numP, int pbase, int koff,
                           int ntiles, int cl, int NCg)
{
    constexpr int KPAD = KK * 32;
    constexpr int SBH = KPAD + 8;
    constexpr int ESZ = 64 * SBH * 2;
    constexpr int OFF_RING = 2 * ESZ;
    constexpr int SSZ = 64 * 80;             // 64 rows x 80B (64 data + 16 pad, swizzle-free)
    constexpr int OFF_RS = OFF_RING + 4 * SSZ;

    extern __shared__ char smem[];
    const uint32_t sb32 = smem_u32(smem);
    float* rs_s = (float*)(smem + OFF_RS);
    const int tid = threadIdx.x, wid = tid >> 5, lane = tid & 31;
    const int wr = wid >> 1, wc = wid & 1;

    // stage E (hi/lo fp16) resident; zero rs_s
    for (int idx = tid; idx < 64 * (KPAD / 2); idx += 256) {
        int b = idx / (KPAD / 2), h = idx % (KPAD / 2), k = 2 * h;
        float2 v = make_float2(0.f, 0.f);
        if (k < KG) v = *(const float2*)&g_E[b * KTOT + koff + k];
        uint32_t h2, l2; cvt_hilo16(v.x, v.y, h2, l2);
        ((uint32_t*)smem)[b * (SBH / 2) + h] = h2;
        ((uint32_t*)(smem + ESZ))[b * (SBH / 2) + h] = l2;
    }
    if (tid < 64) rs_s[tid] = 0.0f;

    const int myT = (cl < ntiles) ? ((ntiles - cl + NCg - 1) / NCg) : 0;
    const int total = myT * KK;

    // one cp.async (16B) per thread per k-step: r = row (p), ch = 16B chunk
    const int r_cp = tid >> 2, ch_cp = tid & 3;
    auto issue = [&](int gs) {
        if (gs >= total) return;
        const int tj = gs / KK, st = gs - tj * KK;
        const int p0 = (cl + tj * NCg) * 64;
        const int kb = st * 64 + ch_cp * 16;          // byte offset within row
        const int p = p0 + r_cp;
        int rem = (p < numP) ? (KG * 2 - kb) : 0;
        int bytes = rem <= 0 ? 0 : (rem >= 16 ? 16 : rem);
        const char* src = (const char*)BmH + (bytes > 0 ? ((size_t)p * KGP2 * 2 + kb) : 0);
        cp_async16(sb32 + OFF_RING + (gs & 3) * SSZ + r_cp * 80 + ch_cp * 16, src, bytes);
    };

    const int m0 = wr * 16 + (lane >> 2), m1 = m0 + 8;
    float gpre[16];
    float acc[4][4];
    float rsacc[8];
#pragma unroll
    for (int t = 0; t < 4; t++)
#pragma unroll
        for (int i = 0; i < 4; i++) acc[t][i] = 0.0f;
#pragma unroll
    for (int j = 0; j < 8; j++) rsacc[j] = 0.0f;

    auto ldg_g = [&](int p0) {
        const int pA = p0 + m0, pB = p0 + m1;
        const bool vA = pA < numP, vB = pB < numP;
        const size_t gA = (size_t)(pbase + pA), gB = (size_t)(pbase + pB);
#pragma unroll
        for (int t = 0; t < 4; t++) {
            int b = wc * 32 + t * 8 + (lane & 3) * 2;
            gpre[4 * t + 0] = vA ? G[(size_t)b * TOTP + gA] : 0.f;
            gpre[4 * t + 1] = vA ? G[(size_t)(b + 1) * TOTP + gA] : 0.f;
            gpre[4 * t + 2] = vB ? G[(size_t)b * TOTP + gB] : 0.f;
            gpre[4 * t + 3] = vB ? G[(size_t)(b + 1) * TOTP + gB] : 0.f;
        }
    };

    issue(0); cp_commit();
    issue(1); cp_commit();
    issue(2); cp_commit();

    int tile = cl;
    for (int gs = 0; gs < total; gs++) {
        cp_wait2();
        __syncthreads();
        const int st = gs % KK;
        if (st == 0) ldg_g(tile * 64);

        const uint32_t aB = sb32 + OFF_RING + (gs & 3) * SSZ;
#pragma unroll
        for (int kk2 = 0; kk2 < 2; kk2++) {
            uint32_t ah[4];
            uint32_t ra = (uint32_t)((wr * 16 + (lane & 15)) * 80 + kk2 * 32 + (lane >> 4) * 16);
            LDSM_X4(ah, aB + ra);
            const int kcol = st * 32 + kk2 * 16;
#pragma unroll
            for (int g = 0; g < 2; g++) {
                uint32_t rb = (uint32_t)((wc * 32 + g * 16 + (lane & 15)) * (SBH * 2) + kcol * 2 + (lane >> 4) * 16);
                uint32_t eh[4], el[4];
                LDSM_X4(eh, sb32 + rb);
                LDSM_X4(el, sb32 + ESZ + rb);
                MMA16816(acc[2 * g],     ah, eh[0], eh[2]);
                MMA16816(acc[2 * g],     ah, el[0], el[2]);
                MMA16816(acc[2 * g + 1], ah, eh[1], eh[3]);
                MMA16816(acc[2 * g + 1], ah, el[1], el[3]);
            }
        }

        issue(gs + 3); cp_commit();

        if (st == KK - 1) {
            const int p0 = tile * 64;
            const int pA = p0 + m0, pB = p0 + m1;
            const bool vA = pA < numP, vB = pB < numP;
            const size_t gA = (size_t)(pbase + pA), gB = (size_t)(pbase + pB);
            float cs0 = 0.f, cs1 = 0.f;
#pragma unroll
            for (int t = 0; t < 4; t++) {
                const int b = wc * 32 + t * 8 + (lane & 3) * 2;
                {
                    float gv0 = gpre[4 * t + 0], gv1 = gpre[4 * t + 1];
                    float r0 = gv0 - acc[t][0], r1 = gv1 - acc[t][1];
                    rsacc[2 * t] += r0 * r0; rsacc[2 * t + 1] += r1 * r1;
                    cs0 += gv0 + gv1;
                    __half2 hh = __floats2half2_rn(r0, r1);
                    uint32_t cur = *(uint32_t*)&hh;
                    uint32_t oth = __shfl_xor_sync(~0u, cur, 4);
                    if (!(lane & 4) && vA) {
                        *(uint32_t*)(g_residH + (size_t)b * TOTP + gA) = __byte_perm(cur, oth, 0x5410);
                        *(uint32_t*)(g_residH + (size_t)(b + 1) * TOTP + gA) = __byte_perm(cur, oth, 0x7632);
                    }
                }
                {
                    float gv0 = gpre[4 * t + 2], gv1 = gpre[4 * t + 3];
                    float r0 = gv0 - acc[t][2], r1 = gv1 - acc[t][3];
                    rsacc[2 * t] += r0 * r0; rsacc[2 * t + 1] += r1 * r1;
                    cs1 += gv0 + gv1;
                    __half2 hh = __floats2half2_rn(r0, r1);
                    uint32_t cur = *(uint32_t*)&hh;
                    uint32_t oth = __shfl_xor_sync(~0u, cur, 4);
                    if (!(lane & 4) && vB) {
                        *(uint32_t*)(g_residH + (size_t)b * TOTP + gB) = __byte_perm(cur, oth, 0x5410);
                        *(uint32_t*)(g_residH + (size_t)(b + 1) * TOTP + gB) = __byte_perm(cur, oth, 0x7632);
                    }
                }
            }
            cs0 += __shfl_xor_sync(~0u, cs0, 1); cs0 += __shfl_xor_sync(~0u, cs0, 2);
            cs1 += __shfl_xor_sync(~0u, cs1, 1); cs1 += __shfl_xor_sync(~0u, cs1, 2);
            if ((lane & 3) == 0) {
                if (vA) atomicAdd(&out_tg[pA], cs0 * (1.0f / BATCH));
                if (vB) atomicAdd(&out_tg[pB], cs1 * (1.0f / BATCH));
            }
#pragma unroll
            for (int t = 0; t < 4; t++)
#pragma unroll
                for (int i = 0; i < 4; i++) acc[t][i] = 0.0f;
            tile += NCg;
        }
    }
    cp_wait0();

    // rsq reduction
#pragma unroll
    for (int j = 0; j < 8; j++) {
        float v = rsacc[j];
        v += __shfl_xor_sync(~0u, v, 4);
        v += __shfl_xor_sync(~0u, v, 8);
        v += __shfl_xor_sync(~0u, v, 16);
        rsacc[j] = v;
    }
    if (lane < 4) {
#pragma unroll
        for (int t = 0; t < 4; t++) {
            atomicAdd(&rs_s[wc * 32 + t * 8 + lane * 2],     rsacc[2 * t]);
            atomicAdd(&rs_s[wc * 32 + t * 8 + lane * 2 + 1], rsacc[2 * t + 1]);
        }
    }
    __syncthreads();
    if (tid < 64) atomicAdd(&g_rsq[tid], rs_s[tid]);
}

__global__ __launch_bounds__(256, 2) void k_gemm2_all(
    const float* __restrict__ G, float* __restrict__ out_tg)
{
    const int bx = blockIdx.x;
    if (bx < 49)       gemm2_body<104,4,104>(G, g_BmH,            out_tg,          100000,      0,   0, 1563, bx,        49);
    else if (bx < 188) gemm2_body<156,5,160>(G, g_BmH + BMH_OFF1, out_tg + 100000, 225000, 100000, 104, 3516, bx - 49,  139);
    else               gemm2_body<138,5,144>(G, g_BmH + BMH_OFF2, out_tg + 325000, 175000, 325000, 260, 2735, bx - 188, 108);
}

// ---------------- launch ----------------
extern "C" void kernel_launch(void* const* d_in, const int* in_sizes, int n_in,
                              void* d_out, int out_size) {
    (void)in_sizes; (void)n_in; (void)out_size;
    const float* G  = (const float*)d_in[0];
    const float* B0 = (const float*)d_in[1];
    const float* B1 = (const float*)d_in[2];
    const float* B2 = (const float*)d_in[3];
    float* out = (float*)d_out;
    float* out_tg = out + 398 + TOTP;

    static bool attr_done = false;
    if (!attr_done) {
        cudaFuncSetAttribute(k_gemm2_all, cudaFuncAttributeMaxDynamicSharedMemorySize, 63744);
        attr_done = true;
    }

    k_init<<<256, 256>>>(out_tg);

    k_gemm1_all<<<828, 256, 41984>>>(G, B0, B1, B2);

    k_embed<<<1, 256>>>(out);

    // smem: 2*ESZ(max 43008) + 4*5120 + 256 = 63744
    k_gemm2_all<<<296, 256, 63744>>>(G, out_tg);

    k_final<<<(TOTP / 8 + 255) / 256, 256>>>(out + 398);
}

// round 11
// speedup vs baseline: 3.0256x; 1.0618x over previous
#include <cuda_runtime.h>
#include <cuda_fp16.h>
#include <cstdint>
#include <math.h>

#define TOTP 500000
#define BATCH 64
#define KTOT 398
#define CLIP0 1.0f
#define CLIP1 1.0f

__device__ float g_E[BATCH * KTOT];
__device__ float g_rsq[BATCH];
__device__ __align__(16) __half g_residH[(size_t)BATCH * TOTP];   // 64MB
// fp16 Bm copies, rows padded to 16B multiples: 104 | 160 | 144 halves per row
#define BMH_OFF1 10400000
#define BMH_OFF2 46400000
__device__ __align__(16) __half g_BmH[71600000];                  // 143MB

// ---------------- helpers ----------------
__device__ __forceinline__ uint32_t smem_u32(const void* p) {
    uint32_t a;
    asm("{ .reg .u64 t; cvta.to.shared.u64 t, %1; cvt.u32.u64 %0, t; }" : "=r"(a) : "l"(p));
    return a;
}
__device__ __forceinline__ uint32_t cvt_h16(float x, float y) {
    __half2 h = __floats2half2_rn(x, y);
    return *(uint32_t*)&h;
}
#define LDSM_X4(r, a) \
    asm volatile("ldmatrix.sync.aligned.m8n8.x4.shared.b16 {%0,%1,%2,%3}, [%4];" \
        : "=r"((r)[0]), "=r"((r)[1]), "=r"((r)[2]), "=r"((r)[3]) : "r"(a))
#define LDSM_X4T(r, a) \
    asm volatile("ldmatrix.sync.aligned.m8n8.x4.trans.shared.b16 {%0,%1,%2,%3}, [%4];" \
        : "=r"((r)[0]), "=r"((r)[1]), "=r"((r)[2]), "=r"((r)[3]) : "r"(a))
#define MMA16816(d, a, b0, b1) \
    asm volatile("mma.sync.aligned.m16n8k16.row.col.f32.f16.f16.f32 " \
        "{%0,%1,%2,%3}, {%4,%5,%6,%7}, {%8,%9}, {%0,%1,%2,%3};" \
        : "+f"((d)[0]), "+f"((d)[1]), "+f"((d)[2]), "+f"((d)[3]) \
        : "r"((a)[0]), "r"((a)[1]), "r"((a)[2]), "r"((a)[3]), "r"(b0), "r"(b1))

__device__ __forceinline__ void cp_async16(uint32_t d, const void* s, int bytes) {
    asm volatile("cp.async.cg.shared.global [%0], [%1], 16, %2;" :: "r"(d), "l"(s), "r"(bytes));
}
__device__ __forceinline__ void cp_commit()  { asm volatile("cp.async.commit_group;" ::: "memory"); }
__device__ __forceinline__ void cp_wait2()   { asm volatile("cp.async.wait_group 2;" ::: "memory"); }
__device__ __forceinline__ void cp_wait0()   { asm volatile("cp.async.wait_group 0;" ::: "memory"); }

// ---------------- small kernels ----------------
__global__ void k_init(float* __restrict__ out_tg) {
    const int i = blockIdx.x * blockDim.x + threadIdx.x;
    const int stride = gridDim.x * blockDim.x;
    for (int t = i; t < TOTP; t += stride) out_tg[t] = 0.0f;
    if (i < BATCH * KTOT) g_E[i] = 0.0f;
    if (i < BATCH) g_rsq[i] = 0.0f;
}

__global__ void k_embed(float* __restrict__ out) {
    __shared__ float scale[BATCH];
    const int tid = threadIdx.x;
    if (tid < BATCH) {
        float s = 0.0f;
        for (int j = 0; j < KTOT; j++) { float v = g_E[tid * KTOT + j]; s += v * v; }
        float n = sqrtf(s);
        scale[tid] = ((n > CLIP0) ? (CLIP0 / n) : 1.0f) * (1.0f / BATCH);
    }
    __syncthreads();
    for (int j = tid; j < KTOT; j += blockDim.x) {
        float s = 0.0f;
        for (int b = 0; b < BATCH; b++) s += g_E[b * KTOT + j] * scale[b];
        out[j] = s;
    }
}

__global__ __launch_bounds__(256) void k_final(float* __restrict__ out_resid) {
    __shared__ float scale[BATCH];
    const int tid = threadIdx.x;
    if (tid < BATCH) {
        float n = sqrtf(g_rsq[tid]);
        scale[tid] = ((n > CLIP1) ? (CLIP1 / n) : 1.0f) * (1.0f / BATCH);
    }
    __syncthreads();
    const int p8 = blockIdx.x * blockDim.x + tid;
    if (p8 < TOTP / 8) {
        float s[8];
#pragma unroll
        for (int j = 0; j < 8; j++) s[j] = 0.0f;
        const size_t base = (size_t)p8 * 8;
#pragma unroll 4
        for (int b = 0; b < BATCH; b++) {
            uint4 v = *(const uint4*)(g_residH + (size_t)b * TOTP + base);
            const float sc = scale[b];
            const uint32_t* w = (const uint32_t*)&v;
#pragma unroll
            for (int q = 0; q < 4; q++) {
                float2 f = __half22float2(*(const __half2*)&w[q]);
                s[2 * q] += f.x * sc; s[2 * q + 1] += f.y * sc;
            }
        }
#pragma unroll
        for (int q = 0; q < 4; q++)
            *(float2*)&out_resid[base + 2 * q] = make_float2(s[2 * q], s[2 * q + 1]);
    }
}

// =============== GEMM1 (single-fp16 HMMA, double-buffered) + fp16 Bm export ===============
// E[b][c] += sum_p G[b][p]*Bm[p][c]; G single fp16, Bm single fp16.
template <int KG, int NPAD, int KGP2>
__device__ void gemm1_body(const float* __restrict__ G, const float* __restrict__ Bm,
                           __half* __restrict__ BmH, int numP, int pbase, int koff,
                           int chunk, int bid)
{
    constexpr int NH = NPAD / 2, NT = NH / 8, NG = NT / 2;
    constexpr int SBH = NPAD + 8;
    constexpr int GSTR = 20;
    constexpr int BN = NPAD / 16;
    constexpr int GBUF = 64 * GSTR * 4;      // 5120 (hi only)
    constexpr int OFF_B = 2 * GBUF;          // 10240
    constexpr int BBUF = 32 * SBH * 2;

    extern __shared__ char smem[];
    const uint32_t sb32 = smem_u32(smem);
    const int tid = threadIdx.x, wid = tid >> 5, lane = tid & 31;
    const int wr = wid >> 1, wc = wid & 1;

    const int pstart = bid * chunk;
    const int pend = min(pstart + chunk, numP);
    const int nsteps = (pend - pstart + 31) >> 5;

    float2 gpre[4];
    float2 bpre[BN];

    auto ldg_step = [&](int pt) {
#pragma unroll
        for (int j = 0; j < 4; j++) {
            int idx = tid + j * 256;
            int b = idx >> 4, pp = idx & 15, p = pt + 2 * pp;
            gpre[j] = (p < pend) ? *(const float2*)&G[(size_t)b * TOTP + pbase + p]
                                 : make_float2(0.f, 0.f);
        }
#pragma unroll
        for (int j = 0; j < BN; j++) {
            int idx = tid + j * 256;
            int k = idx / NH, h = idx % NH, c = 2 * h, p = pt + k;
            bpre[j] = (p < pend && c < KG) ? *(const float2*)&Bm[(size_t)p * KG + c]
                                           : make_float2(0.f, 0.f);
        }
    };
    auto sts_step = [&](int buf, int pt) {
        char* gb = smem + buf * GBUF;
        char* bb = smem + OFF_B + buf * BBUF;
#pragma unroll
        for (int j = 0; j < 4; j++) {
            int idx = tid + j * 256;
            int b = idx >> 4, pp = idx & 15;
            ((uint32_t*)gb)[b * GSTR + pp] = cvt_h16(gpre[j].x, gpre[j].y);
        }
#pragma unroll
        for (int j = 0; j < BN; j++) {
            int idx = tid + j * 256;
            int k = idx / NH, h = idx % NH;
            uint32_t v16 = cvt_h16(bpre[j].x, bpre[j].y);
            ((uint32_t*)bb)[k * (SBH / 2) + h] = v16;
            int p = pt + k;
            if (p < pend && 2 * h < KGP2)
                *(uint32_t*)(BmH + (size_t)p * KGP2 + 2 * h) = v16;
        }
    };

    float acc[NT][4];
#pragma unroll
    for (int t = 0; t < NT; t++)
#pragma unroll
        for (int i = 0; i < 4; i++) acc[t][i] = 0.0f;

    ldg_step(pstart);
    sts_step(0, pstart);
    __syncthreads();

    for (int s = 0; s < nsteps; s++) {
        const int cur = s & 1;
        if (s + 1 < nsteps) ldg_step(pstart + (s + 1) * 32);
        const uint32_t gB = sb32 + cur * GBUF;
        const uint32_t bB = sb32 + OFF_B + cur * BBUF;
#pragma unroll
        for (int kk = 0; kk < 2; kk++) {
            uint32_t ah[4];
            uint32_t ra = (uint32_t)((wr * 16 + (lane & 15)) * 80 + kk * 32 + (lane >> 4) * 16);
            LDSM_X4(ah, gB + ra);
            uint32_t rb = (uint32_t)((kk * 16 + (lane & 15)) * (SBH * 2));
#pragma unroll
            for (int g = 0; g < NG; g++) {
                uint32_t cb = (uint32_t)((wc * NH + g * 16 + (lane >> 4) * 8) * 2);
                uint32_t bh[4];
                LDSM_X4T(bh, bB + rb + cb);
                MMA16816(acc[2 * g],     ah, bh[0], bh[1]);
                MMA16816(acc[2 * g + 1], ah, bh[2], bh[3]);
            }
        }
        if (s + 1 < nsteps) sts_step(cur ^ 1, pstart + (s + 1) * 32);
        __syncthreads();
    }

    const int m0 = wr * 16 + (lane >> 2);
#pragma unroll
    for (int t = 0; t < NT; t++) {
        int n0 = wc * NH + t * 8 + (lane & 3) * 2;
        if (n0 < KG) {
            atomicAdd(&g_E[m0 * KTOT + koff + n0], acc[t][0]);
            atomicAdd(&g_E[(m0 + 8) * KTOT + koff + n0], acc[t][2]);
        }
        if (n0 + 1 < KG) {
            atomicAdd(&g_E[m0 * KTOT + koff + n0 + 1], acc[t][1]);
            atomicAdd(&g_E[(m0 + 8) * KTOT + koff + n0 + 1], acc[t][3]);
        }
    }
}

__global__ __launch_bounds__(256, 2) void k_gemm1_all(
    const float* __restrict__ G, const float* __restrict__ B0,
    const float* __restrict__ B1, const float* __restrict__ B2)
{
    const int bx = blockIdx.x;
    if (bx < 261)      gemm1_body<104,128,104>(G, B0, g_BmH,            100000,      0,   0, 384, bx);
    else if (bx < 554) gemm1_body<156,160,160>(G, B1, g_BmH + BMH_OFF1, 225000, 100000, 104, 768, bx - 261);
    else               gemm1_body<138,160,144>(G, B2, g_BmH + BMH_OFF2, 175000, 325000, 260, 640, bx - 554);
}

// =============== GEMM2: fp16 Bm ring + single-fp16 E =====================================
// D[p][b] = sum_k Bm[p][k]*E[b][k]; tiles of 64 p, k-steps of 32.
template <int KG, int KK, int KGP2>
__device__ void gemm2_body(const float* __restrict__ G, const __half* __restrict__ BmH,
                           float* __restrict__ out_tg, int numP, int pbase, int koff,
                           int ntiles, int cl, int NCg)
{
    constexpr int KPAD = KK * 32;
    constexpr int SBH = KPAD + 8;
    constexpr int ESZ = 64 * SBH * 2;
    constexpr int OFF_RING = ESZ;
    constexpr int SSZ = 64 * 80;             // 64 rows x 80B
    constexpr int OFF_RS = OFF_RING + 4 * SSZ;

    extern __shared__ char smem[];
    const uint32_t sb32 = smem_u32(smem);
    float* rs_s = (float*)(smem + OFF_RS);
    const int tid = threadIdx.x, wid = tid >> 5, lane = tid & 31;
    const int wr = wid >> 1, wc = wid & 1;

    // stage E (single fp16) resident; zero rs_s
    for (int idx = tid; idx < 64 * (KPAD / 2); idx += 256) {
        int b = idx / (KPAD / 2), h = idx % (KPAD / 2), k = 2 * h;
        float2 v = make_float2(0.f, 0.f);
        if (k < KG) v = *(const float2*)&g_E[b * KTOT + koff + k];
        ((uint32_t*)smem)[b * (SBH / 2) + h] = cvt_h16(v.x, v.y);
    }
    if (tid < 64) rs_s[tid] = 0.0f;

    const int myT = (cl < ntiles) ? ((ntiles - cl + NCg - 1) / NCg) : 0;
    const int total = myT * KK;

    const int r_cp = tid >> 2, ch_cp = tid & 3;
    auto issue = [&](int gs) {
        if (gs >= total) return;
        const int tj = gs / KK, st = gs - tj * KK;
        const int p0 = (cl + tj * NCg) * 64;
        const int kb = st * 64 + ch_cp * 16;
        const int p = p0 + r_cp;
        int rem = (p < numP) ? (KG * 2 - kb) : 0;
        int bytes = rem <= 0 ? 0 : (rem >= 16 ? 16 : rem);
        const char* src = (const char*)BmH + (bytes > 0 ? ((size_t)p * KGP2 * 2 + kb) : 0);
        cp_async16(sb32 + OFF_RING + (gs & 3) * SSZ + r_cp * 80 + ch_cp * 16, src, bytes);
    };

    const int m0 = wr * 16 + (lane >> 2), m1 = m0 + 8;
    float gpre[16];
    float acc[4][4];
    float rsacc[8];
#pragma unroll
    for (int t = 0; t < 4; t++)
#pragma unroll
        for (int i = 0; i < 4; i++) acc[t][i] = 0.0f;
#pragma unroll
    for (int j = 0; j < 8; j++) rsacc[j] = 0.0f;

    auto ldg_g = [&](int p0) {
        const int pA = p0 + m0, pB = p0 + m1;
        const bool vA = pA < numP, vB = pB < numP;
        const size_t gA = (size_t)(pbase + pA), gB = (size_t)(pbase + pB);
#pragma unroll
        for (int t = 0; t < 4; t++) {
            int b = wc * 32 + t * 8 + (lane & 3) * 2;
            gpre[4 * t + 0] = vA ? G[(size_t)b * TOTP + gA] : 0.f;
            gpre[4 * t + 1] = vA ? G[(size_t)(b + 1) * TOTP + gA] : 0.f;
            gpre[4 * t + 2] = vB ? G[(size_t)b * TOTP + gB] : 0.f;
            gpre[4 * t + 3] = vB ? G[(size_t)(b + 1) * TOTP + gB] : 0.f;
        }
    };

    issue(0); cp_commit();
    issue(1); cp_commit();
    issue(2); cp_commit();

    int tile = cl;
    for (int gs = 0; gs < total; gs++) {
        cp_wait2();
        __syncthreads();
        const int st = gs % KK;
        if (st == 0) ldg_g(tile * 64);

        const uint32_t aB = sb32 + OFF_RING + (gs & 3) * SSZ;
#pragma unroll
        for (int kk2 = 0; kk2 < 2; kk2++) {
            uint32_t ah[4];
            uint32_t ra = (uint32_t)((wr * 16 + (lane & 15)) * 80 + kk2 * 32 + (lane >> 4) * 16);
            LDSM_X4(ah, aB + ra);
            const int kcol = st * 32 + kk2 * 16;
#pragma unroll
            for (int g = 0; g < 2; g++) {
                uint32_t rb = (uint32_t)((wc * 32 + g * 16 + (lane & 15)) * (SBH * 2) + kcol * 2 + (lane >> 4) * 16);
                uint32_t eh[4];
                LDSM_X4(eh, sb32 + rb);
                MMA16816(acc[2 * g],     ah, eh[0], eh[2]);
                MMA16816(acc[2 * g + 1], ah, eh[1], eh[3]);
            }
        }

        issue(gs + 3); cp_commit();

        if (st == KK - 1) {
            const int p0 = tile * 64;
            const int pA = p0 + m0, pB = p0 + m1;
            const bool vA = pA < numP, vB = pB < numP;
            const size_t gA = (size_t)(pbase + pA), gB = (size_t)(pbase + pB);
            float cs0 = 0.f, cs1 = 0.f;
#pragma unroll
            for (int t = 0; t < 4; t++) {
                const int b = wc * 32 + t * 8 + (lane & 3) * 2;
                {
                    float gv0 = gpre[4 * t + 0], gv1 = gpre[4 * t + 1];
                    float r0 = gv0 - acc[t][0], r1 = gv1 - acc[t][1];
                    rsacc[2 * t] += r0 * r0; rsacc[2 * t + 1] += r1 * r1;
                    cs0 += gv0 + gv1;
                    __half2 hh = __floats2half2_rn(r0, r1);
                    uint32_t cur = *(uint32_t*)&hh;
                    uint32_t oth = __shfl_xor_sync(~0u, cur, 4);
                    if (!(lane & 4) && vA) {
                        *(uint32_t*)(g_residH + (size_t)b * TOTP + gA) = __byte_perm(cur, oth, 0x5410);
                        *(uint32_t*)(g_residH + (size_t)(b + 1) * TOTP + gA) = __byte_perm(cur, oth, 0x7632);
                    }
                }
                {
                    float gv0 = gpre[4 * t + 2], gv1 = gpre[4 * t + 3];
                    float r0 = gv0 - acc[t][2], r1 = gv1 - acc[t][3];
                    rsacc[2 * t] += r0 * r0; rsacc[2 * t + 1] += r1 * r1;
                    cs1 += gv0 + gv1;
                    __half2 hh = __floats2half2_rn(r0, r1);
                    uint32_t cur = *(uint32_t*)&hh;
                    uint32_t oth = __shfl_xor_sync(~0u, cur, 4);
                    if (!(lane & 4) && vB) {
                        *(uint32_t*)(g_residH + (size_t)b * TOTP + gB) = __byte_perm(cur, oth, 0x5410);
                        *(uint32_t*)(g_residH + (size_t)(b + 1) * TOTP + gB) = __byte_perm(cur, oth, 0x7632);
                    }
                }
            }
            cs0 += __shfl_xor_sync(~0u, cs0, 1); cs0 += __shfl_xor_sync(~0u, cs0, 2);
            cs1 += __shfl_xor_sync(~0u, cs1, 1); cs1 += __shfl_xor_sync(~0u, cs1, 2);
            if ((lane & 3) == 0) {
                if (vA) atomicAdd(&out_tg[pA], cs0 * (1.0f / BATCH));
                if (vB) atomicAdd(&out_tg[pB], cs1 * (1.0f / BATCH));
            }
#pragma unroll
            for (int t = 0; t < 4; t++)
#pragma unroll
                for (int i = 0; i < 4; i++) acc[t][i] = 0.0f;
            tile += NCg;
        }
    }
    cp_wait0();

    // rsq reduction
#pragma unroll
    for (int j = 0; j < 8; j++) {
        float v = rsacc[j];
        v += __shfl_xor_sync(~0u, v, 4);
        v += __shfl_xor_sync(~0u, v, 8);
        v += __shfl_xor_sync(~0u, v, 16);
        rsacc[j] = v;
    }
    if (lane < 4) {
#pragma unroll
        for (int t = 0; t < 4; t++) {
            atomicAdd(&rs_s[wc * 32 + t * 8 + lane * 2],     rsacc[2 * t]);
            atomicAdd(&rs_s[wc * 32 + t * 8 + lane * 2 + 1], rsacc[2 * t + 1]);
        }
    }
    __syncthreads();
    if (tid < 64) atomicAdd(&g_rsq[tid], rs_s[tid]);
}

__global__ __launch_bounds__(256, 2) void k_gemm2_all(
    const float* __restrict__ G, float* __restrict__ out_tg)
{
    const int bx = blockIdx.x;
    if (bx < 49)       gemm2_body<104,4,104>(G, g_BmH,            out_tg,          100000,      0,   0, 1563, bx,        49);
    else if (bx < 188) gemm2_body<156,5,160>(G, g_BmH + BMH_OFF1, out_tg + 100000, 225000, 100000, 104, 3516, bx - 49,  139);
    else               gemm2_body<138,5,144>(G, g_BmH + BMH_OFF2, out_tg + 325000, 175000, 325000, 260, 2735, bx - 188, 108);
}

// ---------------- launch ----------------
extern "C" void kernel_launch(void* const* d_in, const int* in_sizes, int n_in,
                              void* d_out, int out_size) {
    (void)in_sizes; (void)n_in; (void)out_size;
    const float* G  = (const float*)d_in[0];
    const float* B0 = (const float*)d_in[1];
    const float* B1 = (const float*)d_in[2];
    const float* B2 = (const float*)d_in[3];
    float* out = (float*)d_out;
    float* out_tg = out + 398 + TOTP;

    static bool attr_done = false;
    if (!attr_done) {
        cudaFuncSetAttribute(k_gemm2_all, cudaFuncAttributeMaxDynamicSharedMemorySize, 42240);
        attr_done = true;
    }

    k_init<<<256, 256>>>(out_tg);

    // gemm1 smem: 10240 + 2*32*(NPAD+8)*2 -> max 31744 (NPAD=160)
    k_gemm1_all<<<828, 256, 31744>>>(G, B0, B1, B2);

    k_embed<<<1, 256>>>(out);

    // gemm2 smem: ESZ(max 21504) + 4*5120 + 256 = 42240
    k_gemm2_all<<<296, 256, 42240>>>(G, out_tg);

    k_final<<<(TOTP / 8 + 255) / 256, 256>>>(out + 398);
}

// round 12
// speedup vs baseline: 3.0791x; 1.0177x over previous
#include <cuda_runtime.h>
#include <cuda_fp16.h>
#include <cstdint>
#include <math.h>

#define TOTP 500000
#define BATCH 64
#define KTOT 398
#define CLIP0 1.0f
#define CLIP1 1.0f

__device__ float g_E[BATCH * KTOT];
__device__ float g_rsq[BATCH];
__device__ __align__(16) __half g_residH[(size_t)BATCH * TOTP];   // 64MB
// fp16 Bm copies, rows padded to 16B multiples: 104 | 160 | 144 halves per row
#define BMH_OFF1 10400000
#define BMH_OFF2 46400000
__device__ __align__(16) __half g_BmH[71600000];                  // 143MB

// ---------------- helpers ----------------
__device__ __forceinline__ uint32_t smem_u32(const void* p) {
    uint32_t a;
    asm("{ .reg .u64 t; cvta.to.shared.u64 t, %1; cvt.u32.u64 %0, t; }" : "=r"(a) : "l"(p));
    return a;
}
__device__ __forceinline__ uint32_t cvt_h16(float x, float y) {
    __half2 h = __floats2half2_rn(x, y);
    return *(uint32_t*)&h;
}
#define LDSM_X4(r, a) \
    asm volatile("ldmatrix.sync.aligned.m8n8.x4.shared.b16 {%0,%1,%2,%3}, [%4];" \
        : "=r"((r)[0]), "=r"((r)[1]), "=r"((r)[2]), "=r"((r)[3]) : "r"(a))
#define LDSM_X4T(r, a) \
    asm volatile("ldmatrix.sync.aligned.m8n8.x4.trans.shared.b16 {%0,%1,%2,%3}, [%4];" \
        : "=r"((r)[0]), "=r"((r)[1]), "=r"((r)[2]), "=r"((r)[3]) : "r"(a))
#define MMA16816(d, a, b0, b1) \
    asm volatile("mma.sync.aligned.m16n8k16.row.col.f32.f16.f16.f32 " \
        "{%0,%1,%2,%3}, {%4,%5,%6,%7}, {%8,%9}, {%0,%1,%2,%3};" \
        : "+f"((d)[0]), "+f"((d)[1]), "+f"((d)[2]), "+f"((d)[3]) \
        : "r"((a)[0]), "r"((a)[1]), "r"((a)[2]), "r"((a)[3]), "r"(b0), "r"(b1))

__device__ __forceinline__ void cp_async16(uint32_t d, const void* s, int bytes) {
    asm volatile("cp.async.cg.shared.global [%0], [%1], 16, %2;" :: "r"(d), "l"(s), "r"(bytes));
}
__device__ __forceinline__ void cp_commit()  { asm volatile("cp.async.commit_group;" ::: "memory"); }
__device__ __forceinline__ void cp_wait2()   { asm volatile("cp.async.wait_group 2;" ::: "memory"); }
__device__ __forceinline__ void cp_wait0()   { asm volatile("cp.async.wait_group 0;" ::: "memory"); }

// ---------------- small kernels ----------------
__global__ void k_init(float* __restrict__ out_tg) {
    const int i = blockIdx.x * blockDim.x + threadIdx.x;
    const int stride = gridDim.x * blockDim.x;
    for (int t = i; t < TOTP; t += stride) out_tg[t] = 0.0f;
    if (i < BATCH * KTOT) g_E[i] = 0.0f;
    if (i < BATCH) g_rsq[i] = 0.0f;
}

__global__ void k_embed(float* __restrict__ out) {
    __shared__ float scale[BATCH];
    const int tid = threadIdx.x;
    if (tid < BATCH) {
        float s = 0.0f;
        for (int j = 0; j < KTOT; j++) { float v = g_E[tid * KTOT + j]; s += v * v; }
        float n = sqrtf(s);
        scale[tid] = ((n > CLIP0) ? (CLIP0 / n) : 1.0f) * (1.0f / BATCH);
    }
    __syncthreads();
    for (int j = tid; j < KTOT; j += blockDim.x) {
        float s = 0.0f;
        for (int b = 0; b < BATCH; b++) s += g_E[b * KTOT + j] * scale[b];
        out[j] = s;
    }
}

__global__ __launch_bounds__(256) void k_final(float* __restrict__ out_resid) {
    __shared__ float scale[BATCH];
    const int tid = threadIdx.x;
    if (tid < BATCH) {
        float n = sqrtf(g_rsq[tid]);
        scale[tid] = ((n > CLIP1) ? (CLIP1 / n) : 1.0f) * (1.0f / BATCH);
    }
    __syncthreads();
    const int p8 = blockIdx.x * blockDim.x + tid;
    if (p8 < TOTP / 8) {
        float s[8];
#pragma unroll
        for (int j = 0; j < 8; j++) s[j] = 0.0f;
        const size_t base = (size_t)p8 * 8;
#pragma unroll 4
        for (int b = 0; b < BATCH; b++) {
            uint4 v = *(const uint4*)(g_residH + (size_t)b * TOTP + base);
            const float sc = scale[b];
            const uint32_t* w = (const uint32_t*)&v;
#pragma unroll
            for (int q = 0; q < 4; q++) {
                float2 f = __half22float2(*(const __half2*)&w[q]);
                s[2 * q] += f.x * sc; s[2 * q + 1] += f.y * sc;
            }
        }
#pragma unroll
        for (int q = 0; q < 4; q++)
            *(float2*)&out_resid[base + 2 * q] = make_float2(s[2 * q], s[2 * q + 1]);
    }
}

// =============== GEMM1 (single-fp16 HMMA, double-buffered) + fp16 Bm export ===============
template <int KG, int NPAD, int KGP2>
__device__ void gemm1_body(const float* __restrict__ G, const float* __restrict__ Bm,
                           __half* __restrict__ BmH, int numP, int pbase, int koff,
                           int chunk, int bid)
{
    constexpr int NH = NPAD / 2, NT = NH / 8, NG = NT / 2;
    constexpr int SBH = NPAD + 8;
    constexpr int GSTR = 20;
    constexpr int BN = NPAD / 16;
    constexpr int GBUF = 64 * GSTR * 4;      // 5120
    constexpr int OFF_B = 2 * GBUF;          // 10240
    constexpr int BBUF = 32 * SBH * 2;

    extern __shared__ char smem[];
    const uint32_t sb32 = smem_u32(smem);
    const int tid = threadIdx.x, wid = tid >> 5, lane = tid & 31;
    const int wr = wid >> 1, wc = wid & 1;

    const int pstart = bid * chunk;
    const int pend = min(pstart + chunk, numP);
    const int nsteps = (pend - pstart + 31) >> 5;

    float2 gpre[4];
    float2 bpre[BN];

    auto ldg_step = [&](int pt) {
#pragma unroll
        for (int j = 0; j < 4; j++) {
            int idx = tid + j * 256;
            int b = idx >> 4, pp = idx & 15, p = pt + 2 * pp;
            gpre[j] = (p < pend) ? *(const float2*)&G[(size_t)b * TOTP + pbase + p]
                                 : make_float2(0.f, 0.f);
        }
#pragma unroll
        for (int j = 0; j < BN; j++) {
            int idx = tid + j * 256;
            int k = idx / NH, h = idx % NH, c = 2 * h, p = pt + k;
            bpre[j] = (p < pend && c < KG) ? *(const float2*)&Bm[(size_t)p * KG + c]
                                           : make_float2(0.f, 0.f);
        }
    };
    auto sts_step = [&](int buf, int pt) {
        char* gb = smem + buf * GBUF;
        char* bb = smem + OFF_B + buf * BBUF;
#pragma unroll
        for (int j = 0; j < 4; j++) {
            int idx = tid + j * 256;
            int b = idx >> 4, pp = idx & 15;
            ((uint32_t*)gb)[b * GSTR + pp] = cvt_h16(gpre[j].x, gpre[j].y);
        }
#pragma unroll
        for (int j = 0; j < BN; j++) {
            int idx = tid + j * 256;
            int k = idx / NH, h = idx % NH;
            uint32_t v16 = cvt_h16(bpre[j].x, bpre[j].y);
            ((uint32_t*)bb)[k * (SBH / 2) + h] = v16;
            int p = pt + k;
            if (p < pend && 2 * h < KGP2)
                *(uint32_t*)(BmH + (size_t)p * KGP2 + 2 * h) = v16;
        }
    };

    float acc[NT][4];
#pragma unroll
    for (int t = 0; t < NT; t++)
#pragma unroll
        for (int i = 0; i < 4; i++) acc[t][i] = 0.0f;

    ldg_step(pstart);
    sts_step(0, pstart);
    __syncthreads();

    for (int s = 0; s < nsteps; s++) {
        const int cur = s & 1;
        if (s + 1 < nsteps) ldg_step(pstart + (s + 1) * 32);
        const uint32_t gB = sb32 + cur * GBUF;
        const uint32_t bB = sb32 + OFF_B + cur * BBUF;
#pragma unroll
        for (int kk = 0; kk < 2; kk++) {
            uint32_t ah[4];
            uint32_t ra = (uint32_t)((wr * 16 + (lane & 15)) * 80 + kk * 32 + (lane >> 4) * 16);
            LDSM_X4(ah, gB + ra);
            uint32_t rb = (uint32_t)((kk * 16 + (lane & 15)) * (SBH * 2));
#pragma unroll
            for (int g = 0; g < NG; g++) {
                uint32_t cb = (uint32_t)((wc * NH + g * 16 + (lane >> 4) * 8) * 2);
                uint32_t bh[4];
                LDSM_X4T(bh, bB + rb + cb);
                MMA16816(acc[2 * g],     ah, bh[0], bh[1]);
                MMA16816(acc[2 * g + 1], ah, bh[2], bh[3]);
            }
        }
        if (s + 1 < nsteps) sts_step(cur ^ 1, pstart + (s + 1) * 32);
        __syncthreads();
    }

    const int m0 = wr * 16 + (lane >> 2);
#pragma unroll
    for (int t = 0; t < NT; t++) {
        int n0 = wc * NH + t * 8 + (lane & 3) * 2;
        if (n0 < KG) {
            atomicAdd(&g_E[m0 * KTOT + koff + n0], acc[t][0]);
            atomicAdd(&g_E[(m0 + 8) * KTOT + koff + n0], acc[t][2]);
        }
        if (n0 + 1 < KG) {
            atomicAdd(&g_E[m0 * KTOT + koff + n0 + 1], acc[t][1]);
            atomicAdd(&g_E[(m0 + 8) * KTOT + koff + n0 + 1], acc[t][3]);
        }
    }
}

__global__ __launch_bounds__(256, 2) void k_gemm1_all(
    const float* __restrict__ G, const float* __restrict__ B0,
    const float* __restrict__ B1, const float* __restrict__ B2)
{
    const int bx = blockIdx.x;
    if (bx < 261)      gemm1_body<104,128,104>(G, B0, g_BmH,            100000,      0,   0, 384, bx);
    else if (bx < 554) gemm1_body<156,160,160>(G, B1, g_BmH + BMH_OFF1, 225000, 100000, 104, 768, bx - 261);
    else               gemm1_body<138,160,144>(G, B2, g_BmH + BMH_OFF2, 175000, 325000, 260, 640, bx - 554);
}

// =============== GEMM2 (transposed): D[b][p] = sum_k E[b][k]*Bm[p][k] =====================
// A = E (register-resident fragments, loaded ONCE), B = Bm fp16 ring via cp.async.
// 8 warps = 4(b16) x 2(p32). Tiles of 64 p, k-steps of 32.
template <int KG, int KK, int KGP2>
__device__ void gemm2_body(const float* __restrict__ G, const __half* __restrict__ BmH,
                           float* __restrict__ out_tg, int numP, int pbase, int koff,
                           int ntiles, int cl, int NCg)
{
    constexpr int KPAD = KK * 32;
    constexpr int NK16 = 2 * KK;
    constexpr int SBH = KPAD + 8;
    constexpr int ESZ = 64 * SBH * 2;
    constexpr int OFF_RING = ESZ;
    constexpr int SSZ = 64 * 80;             // 64 rows x 80B

    extern __shared__ char smem[];
    const uint32_t sb32 = smem_u32(smem);
    const int tid = threadIdx.x, wid = tid >> 5, lane = tid & 31;
    const int wr = wid >> 1, wc = wid & 1;

    // stage E (single fp16)
    for (int idx = tid; idx < 64 * (KPAD / 2); idx += 256) {
        int b = idx / (KPAD / 2), h = idx % (KPAD / 2), k = 2 * h;
        float2 v = make_float2(0.f, 0.f);
        if (k < KG) v = *(const float2*)&g_E[b * KTOT + koff + k];
        ((uint32_t*)smem)[b * (SBH / 2) + h] = cvt_h16(v.x, v.y);
    }
    __syncthreads();

    // load E fragments into registers once: A operand b16 x k16 per window
    uint32_t ef[NK16][4];
#pragma unroll
    for (int j = 0; j < NK16; j++) {
        uint32_t ra = (uint32_t)((wr * 16 + (lane & 15)) * (SBH * 2) + j * 32 + (lane >> 4) * 16);
        LDSM_X4(ef[j], sb32 + ra);
    }

    const int myT = (cl < ntiles) ? ((ntiles - cl + NCg - 1) / NCg) : 0;
    const int total = myT * KK;

    const int r_cp = tid >> 2, ch_cp = tid & 3;
    auto issue = [&](int gs) {
        if (gs >= total) return;
        const int tj = gs / KK, st = gs - tj * KK;
        const int p0 = (cl + tj * NCg) * 64;
        const int kb = st * 64 + ch_cp * 16;
        const int p = p0 + r_cp;
        int rem = (p < numP) ? (KG * 2 - kb) : 0;
        int bytes = rem <= 0 ? 0 : (rem >= 16 ? 16 : rem);
        const char* src = (const char*)BmH + (bytes > 0 ? ((size_t)p * KGP2 * 2 + kb) : 0);
        cp_async16(sb32 + OFF_RING + (gs & 3) * SSZ + r_cp * 80 + ch_cp * 16, src, bytes);
    };

    const int bA = wr * 16 + (lane >> 2), bB = bA + 8;
    const int pofs = wc * 32 + (lane & 3) * 2;     // + t*8
    float gpre[16];                                 // [t][{bA.x,bA.y,bB.x,bB.y}]
    float acc[4][4];
    float rsA = 0.f, rsB = 0.f;
#pragma unroll
    for (int t = 0; t < 4; t++)
#pragma unroll
        for (int i = 0; i < 4; i++) acc[t][i] = 0.0f;

    issue(0); cp_commit();
    issue(1); cp_commit();
    issue(2); cp_commit();

    int gs = 0;
    for (int tile = cl; tile < ntiles; tile += NCg) {
        const int p0 = tile * 64;
        // prefetch G for this tile's epilogue (float2: rows bA,bB, consecutive p pairs)
#pragma unroll
        for (int t = 0; t < 4; t++) {
            int p = p0 + pofs + t * 8;
            bool v = p < numP;
            float2 a = v ? *(const float2*)&G[(size_t)bA * TOTP + pbase + p] : make_float2(0.f, 0.f);
            float2 b = v ? *(const float2*)&G[(size_t)bB * TOTP + pbase + p] : make_float2(0.f, 0.f);
            gpre[4 * t + 0] = a.x; gpre[4 * t + 1] = a.y;
            gpre[4 * t + 2] = b.x; gpre[4 * t + 3] = b.y;
        }

#pragma unroll
        for (int st = 0; st < KK; st++) {
            cp_wait2();
            __syncthreads();
            const uint32_t aB = sb32 + OFF_RING + (gs & 3) * SSZ;
#pragma unroll
            for (int kk2 = 0; kk2 < 2; kk2++) {
                const int j = st * 2 + kk2;
#pragma unroll
                for (int g = 0; g < 2; g++) {
                    uint32_t rb = (uint32_t)((wc * 32 + g * 16 + (lane & 15)) * 80 + kk2 * 32 + (lane >> 4) * 16);
                    uint32_t bh[4];
                    LDSM_X4(bh, aB + rb);
                    MMA16816(acc[2 * g],     ef[j], bh[0], bh[2]);
                    MMA16816(acc[2 * g + 1], ef[j], bh[1], bh[3]);
                }
            }
            issue(gs + 3); cp_commit();
            gs++;
        }

        // epilogue: residual (fp16), rsq, colsum->out_tg atomics
        float cs[8];
#pragma unroll
        for (int t = 0; t < 4; t++) {
            const int p = p0 + pofs + t * 8;
            const bool v = p < numP;
            const size_t gp = (size_t)(pbase + p);
            float gA0 = gpre[4 * t + 0], gA1 = gpre[4 * t + 1];
            float gB0 = gpre[4 * t + 2], gB1 = gpre[4 * t + 3];
            float rA0 = gA0 - acc[t][0], rA1 = gA1 - acc[t][1];
            float rB0 = gB0 - acc[t][2], rB1 = gB1 - acc[t][3];
            if (v) {
                __half2 hA = __floats2half2_rn(rA0, rA1);
                __half2 hB = __floats2half2_rn(rB0, rB1);
                *(uint32_t*)(g_residH + (size_t)bA * TOTP + gp) = *(uint32_t*)&hA;
                *(uint32_t*)(g_residH + (size_t)bB * TOTP + gp) = *(uint32_t*)&hB;
            }
            rsA += rA0 * rA0 + rA1 * rA1;
            rsB += rB0 * rB0 + rB1 * rB1;
            cs[2 * t]     = gA0 + gB0;
            cs[2 * t + 1] = gA1 + gB1;
#pragma unroll
            for (int i = 0; i < 4; i++) acc[t][i] = 0.0f;
        }
        // reduce colsums over the 8 row-groups (lanes differing in bits 2,3,4)
#pragma unroll
        for (int q = 0; q < 8; q++) {
            float v = cs[q];
            v += __shfl_xor_sync(~0u, v, 4);
            v += __shfl_xor_sync(~0u, v, 8);
            v += __shfl_xor_sync(~0u, v, 16);
            cs[q] = v;
        }
        if (lane < 4) {
#pragma unroll
            for (int t = 0; t < 4; t++) {
                int p = p0 + wc * 32 + t * 8 + lane * 2;
                if (p < numP)     atomicAdd(&out_tg[p],     cs[2 * t]     * (1.0f / BATCH));
                if (p + 1 < numP) atomicAdd(&out_tg[p + 1], cs[2 * t + 1] * (1.0f / BATCH));
            }
        }
    }
    cp_wait0();

    // rsq: reduce over lane&3 (p within thread-group), then atomic per row
    rsA += __shfl_xor_sync(~0u, rsA, 1); rsA += __shfl_xor_sync(~0u, rsA, 2);
    rsB += __shfl_xor_sync(~0u, rsB, 1); rsB += __shfl_xor_sync(~0u, rsB, 2);
    if ((lane & 3) == 0) {
        atomicAdd(&g_rsq[bA], rsA);
        atomicAdd(&g_rsq[bB], rsB);
    }
}

__global__ __launch_bounds__(256, 2) void k_gemm2_all(
    const float* __restrict__ G, float* __restrict__ out_tg)
{
    const int bx = blockIdx.x;
    if (bx < 49)       gemm2_body<104,4,104>(G, g_BmH,            out_tg,          100000,      0,   0, 1563, bx,        49);
    else if (bx < 188) gemm2_body<156,5,160>(G, g_BmH + BMH_OFF1, out_tg + 100000, 225000, 100000, 104, 3516, bx - 49,  139);
    else               gemm2_body<138,5,144>(G, g_BmH + BMH_OFF2, out_tg + 325000, 175000, 325000, 260, 2735, bx - 188, 108);
}

// ---------------- launch ----------------
extern "C" void kernel_launch(void* const* d_in, const int* in_sizes, int n_in,
                              void* d_out, int out_size) {
    (void)in_sizes; (void)n_in; (void)out_size;
    const float* G  = (const float*)d_in[0];
    const float* B0 = (const float*)d_in[1];
    const float* B1 = (const float*)d_in[2];
    const float* B2 = (const float*)d_in[3];
    float* out = (float*)d_out;
    float* out_tg = out + 398 + TOTP;

    static bool attr_done = false;
    if (!attr_done) {
        cudaFuncSetAttribute(k_gemm2_all, cudaFuncAttributeMaxDynamicSharedMemorySize, 41984);
        attr_done = true;
    }

    k_init<<<256, 256>>>(out_tg);

    // gemm1 smem: 10240 + 2*32*(NPAD+8)*2 -> max 31744 (NPAD=160)
    k_gemm1_all<<<828, 256, 31744>>>(G, B0, B1, B2);

    k_embed<<<1, 256>>>(out);

    // gemm2 smem: ESZ(max 21504) + 4*5120 = 41984
    k_gemm2_all<<<296, 256, 41984>>>(G, out_tg);

    k_final<<<(TOTP / 8 + 255) / 256, 256>>>(out + 398);
}

// round 13
// speedup vs baseline: 3.4164x; 1.1095x over previous
#include <cuda_runtime.h>
#include <cuda_fp16.h>
#include <cstdint>
#include <math.h>

#define TOTP 500000
#define BATCH 64
#define KTOT 398
#define CLIP0 1.0f
#define CLIP1 1.0f

__device__ float g_E[BATCH * KTOT];
__device__ float g_rsq[BATCH];
__device__ __align__(16) __half g_residH[(size_t)BATCH * TOTP];   // 64MB
// fp16 Bm copies, rows padded to 16B multiples: 104 | 160 | 144 halves per row
#define BMH_OFF1 10400000
#define BMH_OFF2 46400000
__device__ __align__(16) __half g_BmH[71600000];                  // 143MB

// ---------------- helpers ----------------
__device__ __forceinline__ uint32_t smem_u32(const void* p) {
    uint32_t a;
    asm("{ .reg .u64 t; cvta.to.shared.u64 t, %1; cvt.u32.u64 %0, t; }" : "=r"(a) : "l"(p));
    return a;
}
__device__ __forceinline__ uint32_t cvt_h16(float x, float y) {
    __half2 h = __floats2half2_rn(x, y);
    return *(uint32_t*)&h;
}
#define LDSM_X4(r, a) \
    asm volatile("ldmatrix.sync.aligned.m8n8.x4.shared.b16 {%0,%1,%2,%3}, [%4];" \
        : "=r"((r)[0]), "=r"((r)[1]), "=r"((r)[2]), "=r"((r)[3]) : "r"(a))
#define LDSM_X4T(r, a) \
    asm volatile("ldmatrix.sync.aligned.m8n8.x4.trans.shared.b16 {%0,%1,%2,%3}, [%4];" \
        : "=r"((r)[0]), "=r"((r)[1]), "=r"((r)[2]), "=r"((r)[3]) : "r"(a))
#define MMA16816(d, a, b0, b1) \
    asm volatile("mma.sync.aligned.m16n8k16.row.col.f32.f16.f16.f32 " \
        "{%0,%1,%2,%3}, {%4,%5,%6,%7}, {%8,%9}, {%0,%1,%2,%3};" \
        : "+f"((d)[0]), "+f"((d)[1]), "+f"((d)[2]), "+f"((d)[3]) \
        : "r"((a)[0]), "r"((a)[1]), "r"((a)[2]), "r"((a)[3]), "r"(b0), "r"(b1))

__device__ __forceinline__ void cp_async16(uint32_t d, const void* s, int bytes) {
    asm volatile("cp.async.cg.shared.global [%0], [%1], 16, %2;" :: "r"(d), "l"(s), "r"(bytes));
}
__device__ __forceinline__ void cp_commit()  { asm volatile("cp.async.commit_group;" ::: "memory"); }
template <int N>
__device__ __forceinline__ void cp_waitg()   { asm volatile("cp.async.wait_group %0;" :: "n"(N) : "memory"); }

// ---------------- small kernels ----------------
__global__ void k_init(float* __restrict__ out_tg) {
    const int i = blockIdx.x * blockDim.x + threadIdx.x;
    const int stride = gridDim.x * blockDim.x;
    for (int t = i; t < TOTP; t += stride) out_tg[t] = 0.0f;
    if (i < BATCH * KTOT) g_E[i] = 0.0f;
    if (i < BATCH) g_rsq[i] = 0.0f;
}

__global__ void k_embed(float* __restrict__ out) {
    __shared__ float scale[BATCH];
    const int tid = threadIdx.x;
    if (tid < BATCH) {
        float s = 0.0f;
        for (int j = 0; j < KTOT; j++) { float v = g_E[tid * KTOT + j]; s += v * v; }
        float n = sqrtf(s);
        scale[tid] = ((n > CLIP0) ? (CLIP0 / n) : 1.0f) * (1.0f / BATCH);
    }
    __syncthreads();
    for (int j = tid; j < KTOT; j += blockDim.x) {
        float s = 0.0f;
        for (int b = 0; b < BATCH; b++) s += g_E[b * KTOT + j] * scale[b];
        out[j] = s;
    }
}

__global__ __launch_bounds__(256) void k_final(float* __restrict__ out_resid) {
    __shared__ float scale[BATCH];
    const int tid = threadIdx.x;
    if (tid < BATCH) {
        float n = sqrtf(g_rsq[tid]);
        scale[tid] = ((n > CLIP1) ? (CLIP1 / n) : 1.0f) * (1.0f / BATCH);
    }
    __syncthreads();
    const int p8 = blockIdx.x * blockDim.x + tid;
    if (p8 < TOTP / 8) {
        float s[8];
#pragma unroll
        for (int j = 0; j < 8; j++) s[j] = 0.0f;
        const size_t base = (size_t)p8 * 8;
#pragma unroll 4
        for (int b = 0; b < BATCH; b++) {
            uint4 v = *(const uint4*)(g_residH + (size_t)b * TOTP + base);
            const float sc = scale[b];
            const uint32_t* w = (const uint32_t*)&v;
#pragma unroll
            for (int q = 0; q < 4; q++) {
                float2 f = __half22float2(*(const __half2*)&w[q]);
                s[2 * q] += f.x * sc; s[2 * q + 1] += f.y * sc;
            }
        }
#pragma unroll
        for (int q = 0; q < 4; q++)
            *(float2*)&out_resid[base + 2 * q] = make_float2(s[2 * q], s[2 * q + 1]);
    }
}

// =============== GEMM1 (single-fp16 HMMA, double-buffered) + fp16 Bm export ===============
// Persistent split-K: each CTA owns ONE contiguous chunk (single wave).
template <int KG, int NPAD, int KGP2>
__device__ void gemm1_body(const float* __restrict__ G, const float* __restrict__ Bm,
                           __half* __restrict__ BmH, int numP, int pbase, int koff,
                           int chunk, int bid)
{
    constexpr int NH = NPAD / 2, NT = NH / 8, NG = NT / 2;
    constexpr int SBH = NPAD + 8;
    constexpr int GSTR = 20;
    constexpr int BN = NPAD / 16;
    constexpr int GBUF = 64 * GSTR * 4;      // 5120
    constexpr int OFF_B = 2 * GBUF;          // 10240
    constexpr int BBUF = 32 * SBH * 2;

    extern __shared__ char smem[];
    const uint32_t sb32 = smem_u32(smem);
    const int tid = threadIdx.x, wid = tid >> 5, lane = tid & 31;
    const int wr = wid >> 1, wc = wid & 1;

    const int pstart = bid * chunk;
    const int pend = min(pstart + chunk, numP);
    if (pstart >= numP) return;
    const int nsteps = (pend - pstart + 31) >> 5;

    float2 gpre[4];
    float2 bpre[BN];

    auto ldg_step = [&](int pt) {
#pragma unroll
        for (int j = 0; j < 4; j++) {
            int idx = tid + j * 256;
            int b = idx >> 4, pp = idx & 15, p = pt + 2 * pp;
            gpre[j] = (p < pend) ? *(const float2*)&G[(size_t)b * TOTP + pbase + p]
                                 : make_float2(0.f, 0.f);
        }
#pragma unroll
        for (int j = 0; j < BN; j++) {
            int idx = tid + j * 256;
            int k = idx / NH, h = idx % NH, c = 2 * h, p = pt + k;
            bpre[j] = (p < pend && c < KG) ? *(const float2*)&Bm[(size_t)p * KG + c]
                                           : make_float2(0.f, 0.f);
        }
    };
    auto sts_step = [&](int buf, int pt) {
        char* gb = smem + buf * GBUF;
        char* bb = smem + OFF_B + buf * BBUF;
#pragma unroll
        for (int j = 0; j < 4; j++) {
            int idx = tid + j * 256;
            int b = idx >> 4, pp = idx & 15;
            ((uint32_t*)gb)[b * GSTR + pp] = cvt_h16(gpre[j].x, gpre[j].y);
        }
#pragma unroll
        for (int j = 0; j < BN; j++) {
            int idx = tid + j * 256;
            int k = idx / NH, h = idx % NH;
            uint32_t v16 = cvt_h16(bpre[j].x, bpre[j].y);
            ((uint32_t*)bb)[k * (SBH / 2) + h] = v16;
            int p = pt + k;
            if (p < pend && 2 * h < KGP2)
                *(uint32_t*)(BmH + (size_t)p * KGP2 + 2 * h) = v16;
        }
    };

    float acc[NT][4];
#pragma unroll
    for (int t = 0; t < NT; t++)
#pragma unroll
        for (int i = 0; i < 4; i++) acc[t][i] = 0.0f;

    ldg_step(pstart);
    sts_step(0, pstart);
    __syncthreads();

    for (int s = 0; s < nsteps; s++) {
        const int cur = s & 1;
        if (s + 1 < nsteps) ldg_step(pstart + (s + 1) * 32);
        const uint32_t gB = sb32 + cur * GBUF;
        const uint32_t bB = sb32 + OFF_B + cur * BBUF;
#pragma unroll
        for (int kk = 0; kk < 2; kk++) {
            uint32_t ah[4];
            uint32_t ra = (uint32_t)((wr * 16 + (lane & 15)) * 80 + kk * 32 + (lane >> 4) * 16);
            LDSM_X4(ah, gB + ra);
            uint32_t rb = (uint32_t)((kk * 16 + (lane & 15)) * (SBH * 2));
#pragma unroll
            for (int g = 0; g < NG; g++) {
                uint32_t cb = (uint32_t)((wc * NH + g * 16 + (lane >> 4) * 8) * 2);
                uint32_t bh[4];
                LDSM_X4T(bh, bB + rb + cb);
                MMA16816(acc[2 * g],     ah, bh[0], bh[1]);
                MMA16816(acc[2 * g + 1], ah, bh[2], bh[3]);
            }
        }
        if (s + 1 < nsteps) sts_step(cur ^ 1, pstart + (s + 1) * 32);
        __syncthreads();
    }

    const int m0 = wr * 16 + (lane >> 2);
#pragma unroll
    for (int t = 0; t < NT; t++) {
        int n0 = wc * NH + t * 8 + (lane & 3) * 2;
        if (n0 < KG) {
            atomicAdd(&g_E[m0 * KTOT + koff + n0], acc[t][0]);
            atomicAdd(&g_E[(m0 + 8) * KTOT + koff + n0], acc[t][2]);
        }
        if (n0 + 1 < KG) {
            atomicAdd(&g_E[m0 * KTOT + koff + n0 + 1], acc[t][1]);
            atomicAdd(&g_E[(m0 + 8) * KTOT + koff + n0 + 1], acc[t][3]);
        }
    }
}

__global__ __launch_bounds__(256, 2) void k_gemm1_all(
    const float* __restrict__ G, const float* __restrict__ B0,
    const float* __restrict__ B1, const float* __restrict__ B2)
{
    const int bx = blockIdx.x;
    if (bx < 50)       gemm1_body<104,128,104>(G, B0, g_BmH,            100000,      0,   0, 2016, bx);
    else if (bx < 188) gemm1_body<156,160,160>(G, B1, g_BmH + BMH_OFF1, 225000, 100000, 104, 1632, bx - 50);
    else               gemm1_body<138,160,144>(G, B2, g_BmH + BMH_OFF2, 175000, 325000, 260, 1632, bx - 188);
}

// =============== GEMM2 (transposed): D[b][p] = sum_k E[b][k]*Bm[p][k] =====================
// A = E (register fragments, loaded once); B = Bm fp16 via cp.async ring of 8.
// Two k32 steps per wait+sync (paired); tiles of 64 p.
template <int KG, int KK, int KGP2>
__device__ void gemm2_body(const float* __restrict__ G, const __half* __restrict__ BmH,
                           float* __restrict__ out_tg, int numP, int pbase, int koff,
                           int ntiles, int cl, int NCg)
{
    constexpr int KPAD = KK * 32;
    constexpr int NK16 = 2 * KK;
    constexpr int SBH = KPAD + 8;
    constexpr int ESZ = 64 * SBH * 2;
    constexpr int OFF_RING = ESZ;
    constexpr int SSZ = 64 * 80;             // 64 rows x 80B
    constexpr int NPAIR = (KK + 1) / 2;

    extern __shared__ char smem[];
    const uint32_t sb32 = smem_u32(smem);
    const int tid = threadIdx.x, wid = tid >> 5, lane = tid & 31;
    const int wr = wid >> 1, wc = wid & 1;

    // stage E (single fp16)
    for (int idx = tid; idx < 64 * (KPAD / 2); idx += 256) {
        int b = idx / (KPAD / 2), h = idx % (KPAD / 2), k = 2 * h;
        float2 v = make_float2(0.f, 0.f);
        if (k < KG) v = *(const float2*)&g_E[b * KTOT + koff + k];
        ((uint32_t*)smem)[b * (SBH / 2) + h] = cvt_h16(v.x, v.y);
    }
    __syncthreads();

    // load E fragments once
    uint32_t ef[NK16][4];
#pragma unroll
    for (int j = 0; j < NK16; j++) {
        uint32_t ra = (uint32_t)((wr * 16 + (lane & 15)) * (SBH * 2) + j * 32 + (lane >> 4) * 16);
        LDSM_X4(ef[j], sb32 + ra);
    }

    const int myT = (cl < ntiles) ? ((ntiles - cl + NCg - 1) / NCg) : 0;
    const int total = myT * KK;

    const int r_cp = tid >> 2, ch_cp = tid & 3;
    auto issue = [&](int gs) {
        if (gs >= total) return;
        const int tj = gs / KK, st = gs - tj * KK;
        const int p0 = (cl + tj * NCg) * 64;
        const int kb = st * 64 + ch_cp * 16;
        const int p = p0 + r_cp;
        int rem = (p < numP) ? (KG * 2 - kb) : 0;
        int bytes = rem <= 0 ? 0 : (rem >= 16 ? 16 : rem);
        const char* src = (const char*)BmH + (bytes > 0 ? ((size_t)p * KGP2 * 2 + kb) : 0);
        cp_async16(sb32 + OFF_RING + (gs & 7) * SSZ + r_cp * 80 + ch_cp * 16, src, bytes);
    };

    const int bA = wr * 16 + (lane >> 2), bB = bA + 8;
    const int pofs = wc * 32 + (lane & 3) * 2;
    float gpre[16];
    float acc[4][4];
    float rsA = 0.f, rsB = 0.f;
#pragma unroll
    for (int t = 0; t < 4; t++)
#pragma unroll
        for (int i = 0; i < 4; i++) acc[t][i] = 0.0f;

#pragma unroll
    for (int i = 0; i < 6; i++) { issue(i); cp_commit(); }

    int gsb = 0;   // base gs of current tile
    for (int tile = cl; tile < ntiles; tile += NCg) {
        const int p0 = tile * 64;
        // prefetch G for this tile's epilogue
#pragma unroll
        for (int t = 0; t < 4; t++) {
            int p = p0 + pofs + t * 8;
            bool v = p < numP;
            float2 a = v ? *(const float2*)&G[(size_t)bA * TOTP + pbase + p] : make_float2(0.f, 0.f);
            float2 b = v ? *(const float2*)&G[(size_t)bB * TOTP + pbase + p] : make_float2(0.f, 0.f);
            gpre[4 * t + 0] = a.x; gpre[4 * t + 1] = a.y;
            gpre[4 * t + 2] = b.x; gpre[4 * t + 3] = b.y;
        }

#pragma unroll
        for (int sp = 0; sp < NPAIR; sp++) {
            constexpr int M2 = 2;   // pair size (last pair may be 1 when KK odd)
            const bool full = (sp * 2 + 1 < KK);
            if (full) cp_waitg<4>(); else cp_waitg<5>();
            __syncthreads();
#pragma unroll
            for (int u = 0; u < M2; u++) {
                const int st = sp * 2 + u;
                if (st >= KK) break;
                const int gs = gsb + st;
                const uint32_t aB = sb32 + OFF_RING + (gs & 7) * SSZ;
#pragma unroll
                for (int kk2 = 0; kk2 < 2; kk2++) {
                    const int j = st * 2 + kk2;
#pragma unroll
                    for (int g = 0; g < 2; g++) {
                        uint32_t rb = (uint32_t)((wc * 32 + g * 16 + (lane & 15)) * 80 + kk2 * 32 + (lane >> 4) * 16);
                        uint32_t bh[4];
                        LDSM_X4(bh, aB + rb);
                        MMA16816(acc[2 * g],     ef[j], bh[0], bh[2]);
                        MMA16816(acc[2 * g + 1], ef[j], bh[1], bh[3]);
                    }
                }
            }
            // refill consumed slots (reuse distance 8 > 2-in-flight pairs)
            {
                const int gs = gsb + sp * 2;
                issue(gs + 6); cp_commit();
                if (full) { issue(gs + 7); cp_commit(); }
            }
        }
        gsb += KK;

        // epilogue: residual (fp16), rsq, colsum->out_tg atomics
        float cs[8];
#pragma unroll
        for (int t = 0; t < 4; t++) {
            const int p = p0 + pofs + t * 8;
            const bool v = p < numP;
            const size_t gp = (size_t)(pbase + p);
            float gA0 = gpre[4 * t + 0], gA1 = gpre[4 * t + 1];
            float gB0 = gpre[4 * t + 2], gB1 = gpre[4 * t + 3];
            float rA0 = gA0 - acc[t][0], rA1 = gA1 - acc[t][1];
            float rB0 = gB0 - acc[t][2], rB1 = gB1 - acc[t][3];
            if (v) {
                __half2 hA = __floats2half2_rn(rA0, rA1);
                __half2 hB = __floats2half2_rn(rB0, rB1);
                *(uint32_t*)(g_residH + (size_t)bA * TOTP + gp) = *(uint32_t*)&hA;
                *(uint32_t*)(g_residH + (size_t)bB * TOTP + gp) = *(uint32_t*)&hB;
            }
            rsA += rA0 * rA0 + rA1 * rA1;
            rsB += rB0 * rB0 + rB1 * rB1;
            cs[2 * t]     = gA0 + gB0;
            cs[2 * t + 1] = gA1 + gB1;
#pragma unroll
            for (int i = 0; i < 4; i++) acc[t][i] = 0.0f;
        }
#pragma unroll
        for (int q = 0; q < 8; q++) {
            float v = cs[q];
            v += __shfl_xor_sync(~0u, v, 4);
            v += __shfl_xor_sync(~0u, v, 8);
            v += __shfl_xor_sync(~0u, v, 16);
            cs[q] = v;
        }
        if (lane < 4) {
#pragma unroll
            for (int t = 0; t < 4; t++) {
                int p = p0 + wc * 32 + t * 8 + lane * 2;
                if (p < numP)     atomicAdd(&out_tg[p],     cs[2 * t]     * (1.0f / BATCH));
                if (p + 1 < numP) atomicAdd(&out_tg[p + 1], cs[2 * t + 1] * (1.0f / BATCH));
            }
        }
    }
    cp_waitg<0>();

    rsA += __shfl_xor_sync(~0u, rsA, 1); rsA += __shfl_xor_sync(~0u, rsA, 2);
    rsB += __shfl_xor_sync(~0u, rsB, 1); rsB += __shfl_xor_sync(~0u, rsB, 2);
    if ((lane & 3) == 0) {
        atomicAdd(&g_rsq[bA], rsA);
        atomicAdd(&g_rsq[bB], rsB);
    }
}

__global__ __launch_bounds__(256, 2) void k_gemm2_all(
    const float* __restrict__ G, float* __restrict__ out_tg)
{
    const int bx = blockIdx.x;
    if (bx < 49)       gemm2_body<104,4,104>(G, g_BmH,            out_tg,          100000,      0,   0, 1563, bx,        49);
    else if (bx < 188) gemm2_body<156,5,160>(G, g_BmH + BMH_OFF1, out_tg + 100000, 225000, 100000, 104, 3516, bx - 49,  139);
    else               gemm2_body<138,5,144>(G, g_BmH + BMH_OFF2, out_tg + 325000, 175000, 325000, 260, 2735, bx - 188, 108);
}

// ---------------- launch ----------------
extern "C" void kernel_launch(void* const* d_in, const int* in_sizes, int n_in,
                              void* d_out, int out_size) {
    (void)in_sizes; (void)n_in; (void)out_size;
    const float* G  = (const float*)d_in[0];
    const float* B0 = (const float*)d_in[1];
    const float* B1 = (const float*)d_in[2];
    const float* B2 = (const float*)d_in[3];
    float* out = (float*)d_out;
    float* out_tg = out + 398 + TOTP;

    static bool attr_done = false;
    if (!attr_done) {
        cudaFuncSetAttribute(k_gemm2_all, cudaFuncAttributeMaxDynamicSharedMemorySize, 62464);
        attr_done = true;
    }

    k_init<<<256, 256>>>(out_tg);

    // gemm1: persistent, one wave (50+138+108 = 296 CTAs)
    k_gemm1_all<<<296, 256, 31744>>>(G, B0, B1, B2);

    k_embed<<<1, 256>>>(out);

    // gemm2 smem: ESZ(max 21504) + 8*5120 = 62464
    k_gemm2_all<<<296, 256, 62464>>>(G, out_tg);

    k_final<<<(TOTP / 8 + 255) / 256, 256>>>(out + 398);
}